// round 10
// baseline (speedup 1.0000x reference)
#include <cuda_runtime.h>
#include <math.h>
#include <stdint.h>

// ---------------------------------------------------------------------------
// Attention_9070970929715 on sm_103a — tf32 mma.sync pipeline, round 10
//   tf32 conversion at STAGING time (smem holds tf32 bits, inner loops pure
//   LDS+MMA); GEMM double-buffers via register prefetch (LDG overlaps MMA).
// ---------------------------------------------------------------------------

#define SEQ_N   4096
#define MODEL_C 1024
#define QKV_C   3072
#define HEADS   16
#define HDIM    64
#define ATT_SCALE 0.125f

__device__ float g_qkv[SEQ_N * QKV_C];     // [n][3C]
__device__ float g_attn[SEQ_N * MODEL_C];  // [n][C]

// ---------------------------------------------------------------------------
__device__ __forceinline__ uint32_t f2tf32(float f) {
    uint32_t u;
    asm("cvt.rn.tf32.f32 %0, %1;" : "=r"(u) : "f"(f));
    return u;
}
// D += A*B  (m16n8k8, tf32 in, f32 accum)
__device__ __forceinline__ void mma8(float* d, const uint32_t* a, uint32_t b0, uint32_t b1) {
    asm volatile(
        "mma.sync.aligned.m16n8k8.row.col.f32.tf32.tf32.f32 "
        "{%0,%1,%2,%3}, {%4,%5,%6,%7}, {%8,%9}, {%0,%1,%2,%3};"
        : "+f"(d[0]), "+f"(d[1]), "+f"(d[2]), "+f"(d[3])
        : "r"(a[0]), "r"(a[1]), "r"(a[2]), "r"(a[3]), "r"(b0), "r"(b1));
}
__device__ __forceinline__ uint4 cvt4(float4 v) {
    return make_uint4(f2tf32(v.x), f2tf32(v.y), f2tf32(v.z), f2tf32(v.w));
}

// ===========================================================================
// tf32 GEMM: C[M,Nc] = A[M,K] * B[Nc,K]^T (+bias)
// 256 thr, BM=BN=128, BK=16; register-prefetch double buffer;
// smem holds tf32 bits (converted once at STS). Warp grid 2x4 (64x32).
// ===========================================================================
#define GP 20
#define GSTG (128 * GP)                  // words per matrix per stage
#define GEMM_SMEM (4 * GSTG * 4)         // 2 stages x (A,B) = 40960 B

__global__ void __launch_bounds__(256, 2)
gemm_tf32(const float* __restrict__ A, const float* __restrict__ B,
          const float* __restrict__ bias, float* __restrict__ C,
          int M, int Nc, int K)
{
    extern __shared__ uint32_t sg[];
    const int tid  = threadIdx.x;
    const int w    = tid >> 5;
    const int lane = tid & 31;
    const int g    = lane >> 2;
    const int tig  = lane & 3;
    const int bm = blockIdx.y * 128;
    const int bn = blockIdx.x * 128;
    const int wm = (w >> 2) * 64;
    const int wn = (w & 3) * 32;

    float acc[4][4][4];
#pragma unroll
    for (int mi = 0; mi < 4; mi++)
#pragma unroll
        for (int ni = 0; ni < 4; ni++)
#pragma unroll
            for (int j = 0; j < 4; j++) acc[mi][ni][j] = 0.f;

    const int KT = K >> 4;
    const int sr = tid >> 2;          // staging row 0..63 (+64 for p=1)
    const int sc = (tid & 3) << 2;    // staging col 0,4,8,12

    float4 pa[2], pb[2];
    auto ldg = [&](int kt) {
#pragma unroll
        for (int p = 0; p < 2; p++) {
            int r = sr + p * 64;
            pa[p] = *(const float4*)&A[(size_t)(bm + r) * K + kt * 16 + sc];
            pb[p] = *(const float4*)&B[(size_t)(bn + r) * K + kt * 16 + sc];
        }
    };
    auto sts = [&](int s) {
        uint32_t* As = sg + s * 2 * GSTG;
        uint32_t* Bs = As + GSTG;
#pragma unroll
        for (int p = 0; p < 2; p++) {
            int r = sr + p * 64;
            *(uint4*)&As[r * GP + sc] = cvt4(pa[p]);
            *(uint4*)&Bs[r * GP + sc] = cvt4(pb[p]);
        }
    };

    ldg(0);
    sts(0);
    __syncthreads();

    for (int kt = 0; kt < KT; kt++) {
        const int cur = kt & 1;
        if (kt + 1 < KT) ldg(kt + 1);          // overlap with MMAs below

        const uint32_t* As = sg + cur * 2 * GSTG;
        const uint32_t* Bs = As + GSTG;
#pragma unroll
        for (int ks = 0; ks < 2; ks++) {
            const int kc = ks * 8 + tig;
            uint32_t af[4][4], bf[4][2];
#pragma unroll
            for (int mi = 0; mi < 4; mi++) {
                int r0 = wm + mi * 16;
                af[mi][0] = As[(r0 + g) * GP + kc];
                af[mi][1] = As[(r0 + g + 8) * GP + kc];
                af[mi][2] = As[(r0 + g) * GP + kc + 4];
                af[mi][3] = As[(r0 + g + 8) * GP + kc + 4];
            }
#pragma unroll
            for (int ni = 0; ni < 4; ni++) {
                int c0 = wn + ni * 8;
                bf[ni][0] = Bs[(c0 + g) * GP + kc];
                bf[ni][1] = Bs[(c0 + g) * GP + kc + 4];
            }
#pragma unroll
            for (int mi = 0; mi < 4; mi++)
#pragma unroll
                for (int ni = 0; ni < 4; ni++)
                    mma8(acc[mi][ni], af[mi], bf[ni][0], bf[ni][1]);
        }
        if (kt + 1 < KT) sts(cur ^ 1);         // other buffer: no race with readers of cur
        __syncthreads();
    }

#pragma unroll
    for (int mi = 0; mi < 4; mi++) {
        int row = bm + wm + mi * 16 + g;
#pragma unroll
        for (int ni = 0; ni < 4; ni++) {
            int col = bn + wn + ni * 8 + 2 * tig;
            float2 b2 = bias ? *(const float2*)&bias[col] : make_float2(0.f, 0.f);
            *(float2*)&C[(size_t)row * Nc + col] =
                make_float2(acc[mi][ni][0] + b2.x, acc[mi][ni][1] + b2.y);
            *(float2*)&C[(size_t)(row + 8) * Nc + col] =
                make_float2(acc[mi][ni][2] + b2.x, acc[mi][ni][3] + b2.y);
        }
    }
}

// ===========================================================================
// tf32 flash attention, key-permuted K staging, tf32-in-smem.
// grid=(32,16), block=256 (8 warps, warp owns 16 q rows).
// K rows permuted within 8-groups (pi = [0,4,1,5,2,6,3,7]) so the S C-frag
// layout equals the P A-frag layout -> P feeds MMA2 from registers.
// K/V converted to tf32 during staging; inner loop is pure LDS+MMA+exp.
// ===========================================================================
#define KP 68
#define VP 72
#define ATT_SMEM ((128 * KP + 128 * VP) * 4)   // 71680 B -> 2 CTAs/SM

__global__ void __launch_bounds__(256, 2)
flash_mma(const float* __restrict__ qkv, float* __restrict__ out)
{
    extern __shared__ uint32_t su[];
    uint32_t* Ks = su;                 // [128][KP] tf32 bits, rows permuted
    uint32_t* Vs = su + 128 * KP;      // [128][VP] tf32 bits, natural

    const int tid  = threadIdx.x;
    const int w    = tid >> 5;
    const int lane = tid & 31;
    const int g    = lane >> 2;
    const int tig  = lane & 3;
    const int qb   = (int)gridDim.x - 1 - (int)blockIdx.x;  // long CTAs first
    const int h    = blockIdx.y;
    const int qrow0 = qb * 128 + w * 16;
    const int r0g   = qrow0 + g;

    // ---- Q fragments (pre-scaled, tf32) ----
    uint32_t qf[8][4];
    {
        const float* qp = qkv + (size_t)qrow0 * QKV_C + h * HDIM;
#pragma unroll
        for (int ks = 0; ks < 8; ks++) {
            int c = ks * 8 + tig;
            qf[ks][0] = f2tf32(qp[(size_t)g * QKV_C + c] * ATT_SCALE);
            qf[ks][1] = f2tf32(qp[(size_t)(g + 8) * QKV_C + c] * ATT_SCALE);
            qf[ks][2] = f2tf32(qp[(size_t)g * QKV_C + c + 4] * ATT_SCALE);
            qf[ks][3] = f2tf32(qp[(size_t)(g + 8) * QKV_C + c + 4] * ATT_SCALE);
        }
    }

    float acc_o[8][4];
#pragma unroll
    for (int ni = 0; ni < 8; ni++)
#pragma unroll
        for (int j = 0; j < 4; j++) acc_o[ni][j] = 0.f;
    float l0 = 0.f, l1 = 0.f;

    const int sr = tid >> 4;            // staging row 0..15 (stride 16)
    const int scol = (tid & 15) << 2;   // staging col 0..60

    for (int kb = 0; kb <= qb; kb++) {
        __syncthreads();   // prior reads of Ks/Vs complete
        // ---- stage K (permuted rows) and V, tf32-converted ----
        {
            const float* kp = qkv + (size_t)(kb * 128) * QKV_C + MODEL_C + h * HDIM;
#pragma unroll
            for (int p = 0; p < 8; p++) {
                int r = sr + p * 16;
                int rp = (r & ~7) | (((r & 3) << 1) | ((r & 7) >> 2));  // pi^-1
                float4 kv = *(const float4*)(kp + (size_t)r * QKV_C + scol);
                float4 vv = *(const float4*)(kp + (size_t)r * QKV_C + MODEL_C + scol);
                *(uint4*)&Ks[rp * KP + scol] = cvt4(kv);
                *(uint4*)&Vs[r * VP + scol]  = cvt4(vv);
            }
        }
        __syncthreads();

        const bool diag = (kb == qb);
        const int glim = diag ? (2 * w + 2) : 16;   // skip fully-masked key groups
        for (int grp = 0; grp < glim; grp++) {
            // ---- S n-tile: 8 keys, full D=64 ----
            float s4[4] = {0.f, 0.f, 0.f, 0.f};
            const uint32_t* krow = &Ks[(grp * 8 + g) * KP];
#pragma unroll
            for (int ks = 0; ks < 8; ks++) {
                int kc = ks * 8 + tig;
                mma8(s4, qf[ks], krow[kc], krow[kc + 4]);
            }
            // ---- exp + causal mask (keys: p0/p2 -> +tig, p1/p3 -> +tig+4) ----
            float p0 = __expf(s4[0]);
            float p1 = __expf(s4[1]);
            float p2 = __expf(s4[2]);
            float p3 = __expf(s4[3]);
            if (diag) {
                int k0g = kb * 128 + grp * 8 + tig;
                if (k0g > r0g)         p0 = 0.f;
                if (k0g + 4 > r0g)     p1 = 0.f;
                if (k0g > r0g + 8)     p2 = 0.f;
                if (k0g + 4 > r0g + 8) p3 = 0.f;
            }
            l0 += p0 + p1;
            l1 += p2 + p3;
            // ---- P directly as A-fragment: {a0,a1,a2,a3} = {p0,p2,p1,p3} ----
            uint32_t af[4] = { f2tf32(p0), f2tf32(p2), f2tf32(p1), f2tf32(p3) };
            const uint32_t* vr0 = &Vs[(grp * 8 + tig) * VP];
            const uint32_t* vr1 = vr0 + 4 * VP;
#pragma unroll
            for (int ni = 0; ni < 8; ni++) {
                mma8(acc_o[ni], af, vr0[ni * 8 + g], vr1[ni * 8 + g]);
            }
        }
    }

    // ---- finalize: quad-reduce l, normalize, store ----
    l0 += __shfl_xor_sync(0xFFFFFFFFu, l0, 1);
    l0 += __shfl_xor_sync(0xFFFFFFFFu, l0, 2);
    l1 += __shfl_xor_sync(0xFFFFFFFFu, l1, 1);
    l1 += __shfl_xor_sync(0xFFFFFFFFu, l1, 2);
    const float inv0 = 1.f / l0;
    const float inv1 = 1.f / l1;

    float* dst0 = out + (size_t)(qrow0 + g) * MODEL_C + h * HDIM;
    float* dst1 = out + (size_t)(qrow0 + g + 8) * MODEL_C + h * HDIM;
#pragma unroll
    for (int ni = 0; ni < 8; ni++) {
        int col = ni * 8 + 2 * tig;
        *(float2*)&dst0[col] = make_float2(acc_o[ni][0] * inv0, acc_o[ni][1] * inv0);
        *(float2*)&dst1[col] = make_float2(acc_o[ni][2] * inv1, acc_o[ni][3] * inv1);
    }
}

// ===========================================================================
extern "C" void kernel_launch(void* const* d_in, const int* in_sizes, int n_in,
                              void* d_out, int out_size)
{
    const float* x      = (const float*)d_in[0];
    const float* w_qkv  = (const float*)d_in[1];
    const float* w_proj = (const float*)d_in[2];
    const float* b_proj = (const float*)d_in[3];
    float* out = (float*)d_out;

    float* qkv  = nullptr;
    float* attn = nullptr;
    cudaGetSymbolAddress((void**)&qkv,  g_qkv);
    cudaGetSymbolAddress((void**)&attn, g_attn);

    cudaFuncSetAttribute(gemm_tf32, cudaFuncAttributeMaxDynamicSharedMemorySize, GEMM_SMEM);
    cudaFuncSetAttribute(flash_mma, cudaFuncAttributeMaxDynamicSharedMemorySize, ATT_SMEM);

    {   // QKV projection: [4096,3072]
        dim3 grid(QKV_C / 128, SEQ_N / 128);
        gemm_tf32<<<grid, 256, GEMM_SMEM>>>(x, w_qkv, nullptr, qkv, SEQ_N, QKV_C, MODEL_C);
    }
    {   // causal attention -> g_attn
        dim3 grid(SEQ_N / 128, HEADS);
        flash_mma<<<grid, 256, ATT_SMEM>>>(qkv, attn);
    }
    {   // output projection + bias
        dim3 grid(MODEL_C / 128, SEQ_N / 128);
        gemm_tf32<<<grid, 256, GEMM_SMEM>>>(attn, w_proj, b_proj, out, SEQ_N, MODEL_C, MODEL_C);
    }
}

// round 12
// speedup vs baseline: 1.6432x; 1.6432x over previous
#include <cuda_runtime.h>
#include <math.h>
#include <stdint.h>

// ---------------------------------------------------------------------------
// Attention_9070970929715 on sm_103a — round 11
// tf32 as the GLOBAL storage format: prologue rounds x/w_qkv/w_proj to tf32;
// QKV GEMM + flash write tf32-rounded scratch. All hot loops are pure
// cp.async + LDS + mma.sync (zero cvt on any critical path).
// ---------------------------------------------------------------------------

#define SEQ_N   4096
#define MODEL_C 1024
#define QKV_C   3072
#define HEADS   16
#define HDIM    64
#define ATT_SCALE 0.125f   // power of two: exact in tf32

__device__ float g_qkv[SEQ_N * QKV_C];      // tf32-valued [n][3C]
__device__ float g_attn[SEQ_N * MODEL_C];   // tf32-valued [n][C]
__device__ float g_x[SEQ_N * MODEL_C];      // tf32(x)
__device__ float g_wq[QKV_C * MODEL_C];     // tf32(w_qkv)
__device__ float g_wp[MODEL_C * MODEL_C];   // tf32(w_proj)

// ---------------------------------------------------------------------------
__device__ __forceinline__ uint32_t f2tf32(float f) {
    uint32_t u;
    asm("cvt.rn.tf32.f32 %0, %1;" : "=r"(u) : "f"(f));
    return u;
}
__device__ __forceinline__ float rtf(float f) { return __uint_as_float(f2tf32(f)); }
// D += A*B  (m16n8k8, tf32 in, f32 accum)
__device__ __forceinline__ void mma8(float* d, const uint32_t* a, uint32_t b0, uint32_t b1) {
    asm volatile(
        "mma.sync.aligned.m16n8k8.row.col.f32.tf32.tf32.f32 "
        "{%0,%1,%2,%3}, {%4,%5,%6,%7}, {%8,%9}, {%0,%1,%2,%3};"
        : "+f"(d[0]), "+f"(d[1]), "+f"(d[2]), "+f"(d[3])
        : "r"(a[0]), "r"(a[1]), "r"(a[2]), "r"(a[3]), "r"(b0), "r"(b1));
}
__device__ __forceinline__ uint32_t smem_u32(const void* p) {
    return (uint32_t)__cvta_generic_to_shared(p);
}
__device__ __forceinline__ void cp16(uint32_t s, const void* g) {
    asm volatile("cp.async.cg.shared.global [%0], [%1], 16;" :: "r"(s), "l"(g));
}
#define CP_COMMIT() asm volatile("cp.async.commit_group;" ::: "memory")
#define CP_WAIT0()  asm volatile("cp.async.wait_group 0;" ::: "memory")
#define CP_WAIT1()  asm volatile("cp.async.wait_group 1;" ::: "memory")

// ===========================================================================
// Prologue: round fp32 arrays to tf32-valued fp32 (element-wise, float4)
// ===========================================================================
__global__ void __launch_bounds__(256)
cvt_tf32(const float* __restrict__ src, float* __restrict__ dst, int n4)
{
    int i = blockIdx.x * 256 + threadIdx.x;
    if (i < n4) {
        float4 v = ((const float4*)src)[i];
        v.x = rtf(v.x); v.y = rtf(v.y); v.z = rtf(v.z); v.w = rtf(v.w);
        ((float4*)dst)[i] = v;
    }
}

// ===========================================================================
// tf32 GEMM: C[M,Nc] = A[M,K] * B[Nc,K]^T (+bias). Inputs tf32-valued.
// 256 thr, BM=BN=128, BK=32, cp.async double buffer, warp grid 2x4 (64x32).
// cvt_out: round C to tf32 before store (for scratch feeding later stages).
// ===========================================================================
#define GP 36
#define GSTAGE (2 * 128 * GP)
#define GEMM_SMEM (2 * GSTAGE * 4)   // 73728 B

__global__ void __launch_bounds__(256, 2)
gemm_tf32(const float* __restrict__ A, const float* __restrict__ B,
          const float* __restrict__ bias, float* __restrict__ C,
          int M, int Nc, int K, int cvt_out)
{
    extern __shared__ float sg[];
    const int tid  = threadIdx.x;
    const int w    = tid >> 5;
    const int lane = tid & 31;
    const int g    = lane >> 2;
    const int tig  = lane & 3;
    const int bm = blockIdx.y * 128;
    const int bn = blockIdx.x * 128;
    const int wm = (w >> 2) * 64;
    const int wn = (w & 3) * 32;
    const uint32_t sbase = smem_u32(sg);

    float acc[4][4][4];
#pragma unroll
    for (int mi = 0; mi < 4; mi++)
#pragma unroll
        for (int ni = 0; ni < 4; ni++)
#pragma unroll
            for (int j = 0; j < 4; j++) acc[mi][ni][j] = 0.f;

    const int KT = K >> 5;

    auto issue = [&](int kt, int s) {
        const float* Ab = A + (size_t)bm * K + kt * 32;
        const float* Bb = B + (size_t)bn * K + kt * 32;
        uint32_t sa = sbase + (uint32_t)(s * GSTAGE) * 4u;
        uint32_t sb = sa + (uint32_t)(128 * GP) * 4u;
#pragma unroll
        for (int p = 0; p < 4; p++) {
            int idx = tid + p * 256;
            int r   = idx >> 3;
            int c4  = (idx & 7) << 2;
            cp16(sa + (uint32_t)(r * GP + c4) * 4u, Ab + (size_t)r * K + c4);
            cp16(sb + (uint32_t)(r * GP + c4) * 4u, Bb + (size_t)r * K + c4);
        }
        CP_COMMIT();
    };

    issue(0, 0);
    for (int kt = 0; kt < KT; kt++) {
        const int cur = kt & 1;
        if (kt + 1 < KT) { issue(kt + 1, cur ^ 1); CP_WAIT1(); }
        else             { CP_WAIT0(); }
        __syncthreads();

        const uint32_t* As = (const uint32_t*)(sg + cur * GSTAGE);
        const uint32_t* Bs = As + 128 * GP;
#pragma unroll
        for (int ks = 0; ks < 4; ks++) {
            const int kc = ks * 8 + tig;
            uint32_t af[4][4], bf[4][2];
#pragma unroll
            for (int mi = 0; mi < 4; mi++) {
                int r0 = wm + mi * 16;
                af[mi][0] = As[(r0 + g) * GP + kc];
                af[mi][1] = As[(r0 + g + 8) * GP + kc];
                af[mi][2] = As[(r0 + g) * GP + kc + 4];
                af[mi][3] = As[(r0 + g + 8) * GP + kc + 4];
            }
#pragma unroll
            for (int ni = 0; ni < 4; ni++) {
                int c0 = wn + ni * 8;
                bf[ni][0] = Bs[(c0 + g) * GP + kc];
                bf[ni][1] = Bs[(c0 + g) * GP + kc + 4];
            }
#pragma unroll
            for (int mi = 0; mi < 4; mi++)
#pragma unroll
                for (int ni = 0; ni < 4; ni++)
                    mma8(acc[mi][ni], af[mi], bf[ni][0], bf[ni][1]);
        }
        __syncthreads();
    }

#pragma unroll
    for (int mi = 0; mi < 4; mi++) {
        int row = bm + wm + mi * 16 + g;
#pragma unroll
        for (int ni = 0; ni < 4; ni++) {
            int col = bn + wn + ni * 8 + 2 * tig;
            float2 b2 = bias ? *(const float2*)&bias[col] : make_float2(0.f, 0.f);
            float2 v0 = make_float2(acc[mi][ni][0] + b2.x, acc[mi][ni][1] + b2.y);
            float2 v1 = make_float2(acc[mi][ni][2] + b2.x, acc[mi][ni][3] + b2.y);
            if (cvt_out) {
                v0.x = rtf(v0.x); v0.y = rtf(v0.y);
                v1.x = rtf(v1.x); v1.y = rtf(v1.y);
            }
            *(float2*)&C[(size_t)row * Nc + col]       = v0;
            *(float2*)&C[(size_t)(row + 8) * Nc + col] = v1;
        }
    }
}

// ===========================================================================
// tf32 flash attention, key-permuted K staging (pi = [0,4,1,5,2,6,3,7]):
// S C-frag layout == P A-frag layout -> P feeds MMA2 from registers.
// qkv is tf32-valued, so cp.async stages ready-to-use bits; zero cvt in the
// loop except 4 exp->tf32 per 8-key group. Output written tf32-rounded.
// grid=(32,16), block=256 (8 warps x 16 q rows), 2 CTAs/SM.
// ===========================================================================
#define KP 68
#define VP 72
#define ATT_SMEM ((128 * KP + 128 * VP) * 4)   // 71680 B

__global__ void __launch_bounds__(256, 2)
flash_mma(const float* __restrict__ qkv, float* __restrict__ out)
{
    extern __shared__ uint32_t su[];
    uint32_t* Ks = su;                 // [128][KP] tf32 bits, rows permuted
    uint32_t* Vs = su + 128 * KP;      // [128][VP] tf32 bits, natural
    const uint32_t ksb = smem_u32(Ks);
    const uint32_t vsb = smem_u32(Vs);

    const int tid  = threadIdx.x;
    const int w    = tid >> 5;
    const int lane = tid & 31;
    const int g    = lane >> 2;
    const int tig  = lane & 3;
    const int qb   = (int)gridDim.x - 1 - (int)blockIdx.x;  // long CTAs first
    const int h    = blockIdx.y;
    const int qrow0 = qb * 128 + w * 16;
    const int r0g   = qrow0 + g;

    // ---- Q fragments: tf32-valued in gmem; *0.125 is an exact exp shift ----
    uint32_t qf[8][4];
    {
        const float* qp = qkv + (size_t)qrow0 * QKV_C + h * HDIM;
#pragma unroll
        for (int ks = 0; ks < 8; ks++) {
            int c = ks * 8 + tig;
            qf[ks][0] = __float_as_uint(qp[(size_t)g * QKV_C + c] * ATT_SCALE);
            qf[ks][1] = __float_as_uint(qp[(size_t)(g + 8) * QKV_C + c] * ATT_SCALE);
            qf[ks][2] = __float_as_uint(qp[(size_t)g * QKV_C + c + 4] * ATT_SCALE);
            qf[ks][3] = __float_as_uint(qp[(size_t)(g + 8) * QKV_C + c + 4] * ATT_SCALE);
        }
    }

    float acc_o[8][4];
#pragma unroll
    for (int ni = 0; ni < 8; ni++)
#pragma unroll
        for (int j = 0; j < 4; j++) acc_o[ni][j] = 0.f;
    float l0 = 0.f, l1 = 0.f;

    for (int kb = 0; kb <= qb; kb++) {
        __syncthreads();   // prior reads of Ks/Vs complete
        // ---- stage K (permuted rows) and V via cp.async (bits already tf32) ----
        {
            const float* kp = qkv + (size_t)(kb * 128) * QKV_C + MODEL_C + h * HDIM;
#pragma unroll
            for (int p = 0; p < 8; p++) {
                int f = p * 256 + tid;
                int r = f >> 4;
                int c = (f & 15) << 2;
                int rp = (r & ~7) | (((r & 3) << 1) | ((r & 7) >> 2));  // pi^-1
                cp16(ksb + (uint32_t)(rp * KP + c) * 4u, kp + (size_t)r * QKV_C + c);
                cp16(vsb + (uint32_t)(r * VP + c) * 4u,
                     kp + (size_t)r * QKV_C + MODEL_C + c);
            }
            CP_COMMIT();
            CP_WAIT0();
        }
        __syncthreads();

        const bool diag = (kb == qb);
        const int glim = diag ? (2 * w + 2) : 16;   // skip fully-masked key groups
        for (int grp = 0; grp < glim; grp++) {
            // ---- S n-tile: 8 keys, full D=64 ----
            float s4[4] = {0.f, 0.f, 0.f, 0.f};
            const uint32_t* krow = &Ks[(grp * 8 + g) * KP];
#pragma unroll
            for (int ks = 0; ks < 8; ks++) {
                int kc = ks * 8 + tig;
                mma8(s4, qf[ks], krow[kc], krow[kc + 4]);
            }
            // ---- exp + causal mask (keys: p0/p2 -> +tig, p1/p3 -> +tig+4) ----
            float p0 = __expf(s4[0]);
            float p1 = __expf(s4[1]);
            float p2 = __expf(s4[2]);
            float p3 = __expf(s4[3]);
            if (diag) {
                int k0g = kb * 128 + grp * 8 + tig;
                if (k0g > r0g)         p0 = 0.f;
                if (k0g + 4 > r0g)     p1 = 0.f;
                if (k0g > r0g + 8)     p2 = 0.f;
                if (k0g + 4 > r0g + 8) p3 = 0.f;
            }
            l0 += p0 + p1;
            l1 += p2 + p3;
            // ---- P directly as A-fragment: {a0,a1,a2,a3} = {p0,p2,p1,p3} ----
            uint32_t af[4] = { f2tf32(p0), f2tf32(p2), f2tf32(p1), f2tf32(p3) };
            const uint32_t* vr0 = &Vs[(grp * 8 + tig) * VP];
            const uint32_t* vr1 = vr0 + 4 * VP;
#pragma unroll
            for (int ni = 0; ni < 8; ni++) {
                mma8(acc_o[ni], af, vr0[ni * 8 + g], vr1[ni * 8 + g]);
            }
        }
    }

    // ---- finalize: quad-reduce l, normalize, store (tf32-rounded) ----
    l0 += __shfl_xor_sync(0xFFFFFFFFu, l0, 1);
    l0 += __shfl_xor_sync(0xFFFFFFFFu, l0, 2);
    l1 += __shfl_xor_sync(0xFFFFFFFFu, l1, 1);
    l1 += __shfl_xor_sync(0xFFFFFFFFu, l1, 2);
    const float inv0 = 1.f / l0;
    const float inv1 = 1.f / l1;

    float* dst0 = out + (size_t)(qrow0 + g) * MODEL_C + h * HDIM;
    float* dst1 = out + (size_t)(qrow0 + g + 8) * MODEL_C + h * HDIM;
#pragma unroll
    for (int ni = 0; ni < 8; ni++) {
        int col = ni * 8 + 2 * tig;
        *(float2*)&dst0[col] = make_float2(rtf(acc_o[ni][0] * inv0), rtf(acc_o[ni][1] * inv0));
        *(float2*)&dst1[col] = make_float2(rtf(acc_o[ni][2] * inv1), rtf(acc_o[ni][3] * inv1));
    }
}

// ===========================================================================
extern "C" void kernel_launch(void* const* d_in, const int* in_sizes, int n_in,
                              void* d_out, int out_size)
{
    const float* x      = (const float*)d_in[0];
    const float* w_qkv  = (const float*)d_in[1];
    const float* w_proj = (const float*)d_in[2];
    const float* b_proj = (const float*)d_in[3];
    float* out = (float*)d_out;

    float *qkv, *attn, *xt, *wq, *wp;
    cudaGetSymbolAddress((void**)&qkv,  g_qkv);
    cudaGetSymbolAddress((void**)&attn, g_attn);
    cudaGetSymbolAddress((void**)&xt,   g_x);
    cudaGetSymbolAddress((void**)&wq,   g_wq);
    cudaGetSymbolAddress((void**)&wp,   g_wp);

    cudaFuncSetAttribute(gemm_tf32, cudaFuncAttributeMaxDynamicSharedMemorySize, GEMM_SMEM);
    cudaFuncSetAttribute(flash_mma, cudaFuncAttributeMaxDynamicSharedMemorySize, ATT_SMEM);

    {   // prologue: tf32-round inputs
        int n4x = SEQ_N * MODEL_C / 4;
        int n4q = QKV_C * MODEL_C / 4;
        int n4p = MODEL_C * MODEL_C / 4;
        cvt_tf32<<<(n4x + 255) / 256, 256>>>(x, xt, n4x);
        cvt_tf32<<<(n4q + 255) / 256, 256>>>(w_qkv, wq, n4q);
        cvt_tf32<<<(n4p + 255) / 256, 256>>>(w_proj, wp, n4p);
    }
    {   // QKV projection (output tf32-rounded)
        dim3 grid(QKV_C / 128, SEQ_N / 128);
        gemm_tf32<<<grid, 256, GEMM_SMEM>>>(xt, wq, nullptr, qkv,
                                            SEQ_N, QKV_C, MODEL_C, 1);
    }
    {   // causal attention -> g_attn (tf32-rounded)
        dim3 grid(SEQ_N / 128, HEADS);
        flash_mma<<<grid, 256, ATT_SMEM>>>(qkv, attn);
    }
    {   // output projection + bias (fp32 out)
        dim3 grid(MODEL_C / 128, SEQ_N / 128);
        gemm_tf32<<<grid, 256, GEMM_SMEM>>>(attn, wp, b_proj, out,
                                            SEQ_N, MODEL_C, MODEL_C, 0);
    }
}

// round 13
// speedup vs baseline: 1.6803x; 1.0226x over previous
#include <cuda_runtime.h>
#include <math.h>
#include <stdint.h>

// ---------------------------------------------------------------------------
// Attention_9070970929715 on sm_103a — round 13
// tf32 global storage (prologue rounds inputs). GEMM: 64x64 warp tiles
// (4 warps/CTA) to halve smem-crossbar fragment duplication. Flash: split
// S accumulator chains + unroll-2 group pipeline.
// ---------------------------------------------------------------------------

#define SEQ_N   4096
#define MODEL_C 1024
#define QKV_C   3072
#define HEADS   16
#define HDIM    64
#define ATT_SCALE 0.125f   // power of two: exact in tf32

__device__ float g_qkv[SEQ_N * QKV_C];      // tf32-valued [n][3C]
__device__ float g_attn[SEQ_N * MODEL_C];   // tf32-valued [n][C]
__device__ float g_x[SEQ_N * MODEL_C];      // tf32(x)
__device__ float g_wq[QKV_C * MODEL_C];     // tf32(w_qkv)
__device__ float g_wp[MODEL_C * MODEL_C];   // tf32(w_proj)

// ---------------------------------------------------------------------------
__device__ __forceinline__ uint32_t f2tf32(float f) {
    uint32_t u;
    asm("cvt.rn.tf32.f32 %0, %1;" : "=r"(u) : "f"(f));
    return u;
}
__device__ __forceinline__ float rtf(float f) { return __uint_as_float(f2tf32(f)); }
// D += A*B  (m16n8k8, tf32 in, f32 accum)
__device__ __forceinline__ void mma8(float* d, const uint32_t* a, uint32_t b0, uint32_t b1) {
    asm volatile(
        "mma.sync.aligned.m16n8k8.row.col.f32.tf32.tf32.f32 "
        "{%0,%1,%2,%3}, {%4,%5,%6,%7}, {%8,%9}, {%0,%1,%2,%3};"
        : "+f"(d[0]), "+f"(d[1]), "+f"(d[2]), "+f"(d[3])
        : "r"(a[0]), "r"(a[1]), "r"(a[2]), "r"(a[3]), "r"(b0), "r"(b1));
}
__device__ __forceinline__ uint32_t smem_u32(const void* p) {
    return (uint32_t)__cvta_generic_to_shared(p);
}
__device__ __forceinline__ void cp16(uint32_t s, const void* g) {
    asm volatile("cp.async.cg.shared.global [%0], [%1], 16;" :: "r"(s), "l"(g));
}
#define CP_COMMIT() asm volatile("cp.async.commit_group;" ::: "memory")
#define CP_WAIT0()  asm volatile("cp.async.wait_group 0;" ::: "memory")
#define CP_WAIT1()  asm volatile("cp.async.wait_group 1;" ::: "memory")

// ===========================================================================
// Prologue: round fp32 arrays to tf32-valued fp32
// ===========================================================================
__global__ void __launch_bounds__(256)
cvt_tf32(const float* __restrict__ src, float* __restrict__ dst, int n4)
{
    int i = blockIdx.x * 256 + threadIdx.x;
    if (i < n4) {
        float4 v = ((const float4*)src)[i];
        v.x = rtf(v.x); v.y = rtf(v.y); v.z = rtf(v.z); v.w = rtf(v.w);
        ((float4*)dst)[i] = v;
    }
}

// ===========================================================================
// tf32 GEMM: C[M,Nc] = A[M,K] * B[Nc,K]^T (+bias). Inputs tf32-valued.
// 128 thr (4 warps), BM=BN=128, BK=32, cp.async double buffer.
// Warp grid 2x2, warp tile 64x64: halves smem fragment duplication.
// ===========================================================================
#define GP 36
#define GSTAGE (2 * 128 * GP)
#define GEMM_SMEM (2 * GSTAGE * 4)   // 73728 B

__global__ void __launch_bounds__(128, 2)
gemm_tf32(const float* __restrict__ A, const float* __restrict__ B,
          const float* __restrict__ bias, float* __restrict__ C,
          int M, int Nc, int K, int cvt_out)
{
    extern __shared__ float sg[];
    const int tid  = threadIdx.x;
    const int w    = tid >> 5;
    const int lane = tid & 31;
    const int g    = lane >> 2;
    const int tig  = lane & 3;
    const int bm = blockIdx.y * 128;
    const int bn = blockIdx.x * 128;
    const int wm = (w >> 1) * 64;
    const int wn = (w & 1) * 64;
    const uint32_t sbase = smem_u32(sg);

    float acc[4][8][4];
#pragma unroll
    for (int mi = 0; mi < 4; mi++)
#pragma unroll
        for (int ni = 0; ni < 8; ni++)
#pragma unroll
            for (int j = 0; j < 4; j++) acc[mi][ni][j] = 0.f;

    const int KT = K >> 5;

    auto issue = [&](int kt, int s) {
        const float* Ab = A + (size_t)bm * K + kt * 32;
        const float* Bb = B + (size_t)bn * K + kt * 32;
        uint32_t sa = sbase + (uint32_t)(s * GSTAGE) * 4u;
        uint32_t sb = sa + (uint32_t)(128 * GP) * 4u;
#pragma unroll
        for (int p = 0; p < 8; p++) {
            int idx = tid + p * 128;        // 0..1023
            int r   = idx >> 3;             // 0..127
            int c4  = (idx & 7) << 2;       // 0,4,...,28
            cp16(sa + (uint32_t)(r * GP + c4) * 4u, Ab + (size_t)r * K + c4);
            cp16(sb + (uint32_t)(r * GP + c4) * 4u, Bb + (size_t)r * K + c4);
        }
        CP_COMMIT();
    };

    issue(0, 0);
    for (int kt = 0; kt < KT; kt++) {
        const int cur = kt & 1;
        if (kt + 1 < KT) { issue(kt + 1, cur ^ 1); CP_WAIT1(); }
        else             { CP_WAIT0(); }
        __syncthreads();

        const uint32_t* As = (const uint32_t*)(sg + cur * GSTAGE);
        const uint32_t* Bs = As + 128 * GP;
#pragma unroll
        for (int ks = 0; ks < 4; ks++) {
            const int kc = ks * 8 + tig;
            uint32_t af[4][4], bf[8][2];
#pragma unroll
            for (int mi = 0; mi < 4; mi++) {
                int r0 = wm + mi * 16;
                af[mi][0] = As[(r0 + g) * GP + kc];
                af[mi][1] = As[(r0 + g + 8) * GP + kc];
                af[mi][2] = As[(r0 + g) * GP + kc + 4];
                af[mi][3] = As[(r0 + g + 8) * GP + kc + 4];
            }
#pragma unroll
            for (int ni = 0; ni < 8; ni++) {
                int c0 = wn + ni * 8;
                bf[ni][0] = Bs[(c0 + g) * GP + kc];
                bf[ni][1] = Bs[(c0 + g) * GP + kc + 4];
            }
#pragma unroll
            for (int mi = 0; mi < 4; mi++)
#pragma unroll
                for (int ni = 0; ni < 8; ni++)
                    mma8(acc[mi][ni], af[mi], bf[ni][0], bf[ni][1]);
        }
        __syncthreads();
    }

#pragma unroll
    for (int mi = 0; mi < 4; mi++) {
        int row = bm + wm + mi * 16 + g;
#pragma unroll
        for (int ni = 0; ni < 8; ni++) {
            int col = bn + wn + ni * 8 + 2 * tig;
            float2 b2 = bias ? *(const float2*)&bias[col] : make_float2(0.f, 0.f);
            float2 v0 = make_float2(acc[mi][ni][0] + b2.x, acc[mi][ni][1] + b2.y);
            float2 v1 = make_float2(acc[mi][ni][2] + b2.x, acc[mi][ni][3] + b2.y);
            if (cvt_out) {
                v0.x = rtf(v0.x); v0.y = rtf(v0.y);
                v1.x = rtf(v1.x); v1.y = rtf(v1.y);
            }
            *(float2*)&C[(size_t)row * Nc + col]       = v0;
            *(float2*)&C[(size_t)(row + 8) * Nc + col] = v1;
        }
    }
}

// ===========================================================================
// tf32 flash attention, key-permuted K staging (pi = [0,4,1,5,2,6,3,7]):
// S C-frag layout == P A-frag layout -> P feeds MMA2 from registers.
// S computed with two split accumulator chains (depth 4 each); group loop
// unrolled x2 (glim always even) so MMA1(g+1) overlaps MMA2(g).
// grid=(32,16), block=256 (8 warps x 16 q rows), 2 CTAs/SM.
// ===========================================================================
#define KP 68
#define VP 72
#define ATT_SMEM ((128 * KP + 128 * VP) * 4)   // 71680 B

__global__ void __launch_bounds__(256, 2)
flash_mma(const float* __restrict__ qkv, float* __restrict__ out)
{
    extern __shared__ uint32_t su[];
    uint32_t* Ks = su;                 // [128][KP] tf32 bits, rows permuted
    uint32_t* Vs = su + 128 * KP;      // [128][VP] tf32 bits, natural
    const uint32_t ksb = smem_u32(Ks);
    const uint32_t vsb = smem_u32(Vs);

    const int tid  = threadIdx.x;
    const int w    = tid >> 5;
    const int lane = tid & 31;
    const int g    = lane >> 2;
    const int tig  = lane & 3;
    const int qb   = (int)gridDim.x - 1 - (int)blockIdx.x;  // long CTAs first
    const int h    = blockIdx.y;
    const int qrow0 = qb * 128 + w * 16;
    const int r0g   = qrow0 + g;

    // ---- Q fragments: tf32-valued in gmem; *0.125 exact ----
    uint32_t qf[8][4];
    {
        const float* qp = qkv + (size_t)qrow0 * QKV_C + h * HDIM;
#pragma unroll
        for (int ks = 0; ks < 8; ks++) {
            int c = ks * 8 + tig;
            qf[ks][0] = __float_as_uint(qp[(size_t)g * QKV_C + c] * ATT_SCALE);
            qf[ks][1] = __float_as_uint(qp[(size_t)(g + 8) * QKV_C + c] * ATT_SCALE);
            qf[ks][2] = __float_as_uint(qp[(size_t)g * QKV_C + c + 4] * ATT_SCALE);
            qf[ks][3] = __float_as_uint(qp[(size_t)(g + 8) * QKV_C + c + 4] * ATT_SCALE);
        }
    }

    float acc_o[8][4];
#pragma unroll
    for (int ni = 0; ni < 8; ni++)
#pragma unroll
        for (int j = 0; j < 4; j++) acc_o[ni][j] = 0.f;
    float l0 = 0.f, l1 = 0.f;

    for (int kb = 0; kb <= qb; kb++) {
        __syncthreads();   // prior reads of Ks/Vs complete
        // ---- stage K (permuted rows) and V via cp.async (bits already tf32) ----
        {
            const float* kp = qkv + (size_t)(kb * 128) * QKV_C + MODEL_C + h * HDIM;
#pragma unroll
            for (int p = 0; p < 8; p++) {
                int f = p * 256 + tid;
                int r = f >> 4;
                int c = (f & 15) << 2;
                int rp = (r & ~7) | (((r & 3) << 1) | ((r & 7) >> 2));  // pi^-1
                cp16(ksb + (uint32_t)(rp * KP + c) * 4u, kp + (size_t)r * QKV_C + c);
                cp16(vsb + (uint32_t)(r * VP + c) * 4u,
                     kp + (size_t)r * QKV_C + MODEL_C + c);
            }
            CP_COMMIT();
            CP_WAIT0();
        }
        __syncthreads();

        const bool diag = (kb == qb);
        const int glim = diag ? (2 * w + 2) : 16;   // always even
#pragma unroll 2
        for (int grp = 0; grp < glim; grp++) {
            // ---- S n-tile: 8 keys, full D=64; two split chains ----
            float s4a[4] = {0.f, 0.f, 0.f, 0.f};
            float s4b[4] = {0.f, 0.f, 0.f, 0.f};
            const uint32_t* krow = &Ks[(grp * 8 + g) * KP];
#pragma unroll
            for (int ks = 0; ks < 4; ks++) {
                int kc0 = (2 * ks) * 8 + tig;
                int kc1 = (2 * ks + 1) * 8 + tig;
                mma8(s4a, qf[2 * ks],     krow[kc0], krow[kc0 + 4]);
                mma8(s4b, qf[2 * ks + 1], krow[kc1], krow[kc1 + 4]);
            }
            // ---- exp + causal mask (keys: p0/p2 -> +tig, p1/p3 -> +tig+4) ----
            float p0 = __expf(s4a[0] + s4b[0]);
            float p1 = __expf(s4a[1] + s4b[1]);
            float p2 = __expf(s4a[2] + s4b[2]);
            float p3 = __expf(s4a[3] + s4b[3]);
            if (diag) {
                int k0g = kb * 128 + grp * 8 + tig;
                if (k0g > r0g)         p0 = 0.f;
                if (k0g + 4 > r0g)     p1 = 0.f;
                if (k0g > r0g + 8)     p2 = 0.f;
                if (k0g + 4 > r0g + 8) p3 = 0.f;
            }
            l0 += p0 + p1;
            l1 += p2 + p3;
            // ---- P directly as A-fragment: {a0,a1,a2,a3} = {p0,p2,p1,p3} ----
            uint32_t af[4] = { f2tf32(p0), f2tf32(p2), f2tf32(p1), f2tf32(p3) };
            const uint32_t* vr0 = &Vs[(grp * 8 + tig) * VP];
            const uint32_t* vr1 = vr0 + 4 * VP;
#pragma unroll
            for (int ni = 0; ni < 8; ni++) {
                mma8(acc_o[ni], af, vr0[ni * 8 + g], vr1[ni * 8 + g]);
            }
        }
    }

    // ---- finalize: quad-reduce l, normalize, store (tf32-rounded) ----
    l0 += __shfl_xor_sync(0xFFFFFFFFu, l0, 1);
    l0 += __shfl_xor_sync(0xFFFFFFFFu, l0, 2);
    l1 += __shfl_xor_sync(0xFFFFFFFFu, l1, 1);
    l1 += __shfl_xor_sync(0xFFFFFFFFu, l1, 2);
    const float inv0 = 1.f / l0;
    const float inv1 = 1.f / l1;

    float* dst0 = out + (size_t)(qrow0 + g) * MODEL_C + h * HDIM;
    float* dst1 = out + (size_t)(qrow0 + g + 8) * MODEL_C + h * HDIM;
#pragma unroll
    for (int ni = 0; ni < 8; ni++) {
        int col = ni * 8 + 2 * tig;
        *(float2*)&dst0[col] = make_float2(rtf(acc_o[ni][0] * inv0), rtf(acc_o[ni][1] * inv0));
        *(float2*)&dst1[col] = make_float2(rtf(acc_o[ni][2] * inv1), rtf(acc_o[ni][3] * inv1));
    }
}

// ===========================================================================
extern "C" void kernel_launch(void* const* d_in, const int* in_sizes, int n_in,
                              void* d_out, int out_size)
{
    const float* x      = (const float*)d_in[0];
    const float* w_qkv  = (const float*)d_in[1];
    const float* w_proj = (const float*)d_in[2];
    const float* b_proj = (const float*)d_in[3];
    float* out = (float*)d_out;

    float *qkv, *attn, *xt, *wq, *wp;
    cudaGetSymbolAddress((void**)&qkv,  g_qkv);
    cudaGetSymbolAddress((void**)&attn, g_attn);
    cudaGetSymbolAddress((void**)&xt,   g_x);
    cudaGetSymbolAddress((void**)&wq,   g_wq);
    cudaGetSymbolAddress((void**)&wp,   g_wp);

    cudaFuncSetAttribute(gemm_tf32, cudaFuncAttributeMaxDynamicSharedMemorySize, GEMM_SMEM);
    cudaFuncSetAttribute(flash_mma, cudaFuncAttributeMaxDynamicSharedMemorySize, ATT_SMEM);

    {   // prologue: tf32-round inputs
        int n4x = SEQ_N * MODEL_C / 4;
        int n4q = QKV_C * MODEL_C / 4;
        int n4p = MODEL_C * MODEL_C / 4;
        cvt_tf32<<<(n4x + 255) / 256, 256>>>(x, xt, n4x);
        cvt_tf32<<<(n4q + 255) / 256, 256>>>(w_qkv, wq, n4q);
        cvt_tf32<<<(n4p + 255) / 256, 256>>>(w_proj, wp, n4p);
    }
    {   // QKV projection (output tf32-rounded)
        dim3 grid(QKV_C / 128, SEQ_N / 128);
        gemm_tf32<<<grid, 128, GEMM_SMEM>>>(xt, wq, nullptr, qkv,
                                            SEQ_N, QKV_C, MODEL_C, 1);
    }
    {   // causal attention -> g_attn (tf32-rounded)
        dim3 grid(SEQ_N / 128, HEADS);
        flash_mma<<<grid, 256, ATT_SMEM>>>(qkv, attn);
    }
    {   // output projection + bias (fp32 out)
        dim3 grid(MODEL_C / 128, SEQ_N / 128);
        gemm_tf32<<<grid, 128, GEMM_SMEM>>>(attn, wp, b_proj, out,
                                            SEQ_N, MODEL_C, MODEL_C, 0);
    }
}

// round 14
// speedup vs baseline: 1.7243x; 1.0261x over previous
#include <cuda_runtime.h>
#include <math.h>
#include <stdint.h>

// ---------------------------------------------------------------------------
// Attention_9070970929715 on sm_103a — round 14
// tf32 global storage. GEMM: 3-stage cp.async ring, single barrier per tile.
// Flash: K/V double-buffered across k-blocks (staging latency hidden).
// ---------------------------------------------------------------------------

#define SEQ_N   4096
#define MODEL_C 1024
#define QKV_C   3072
#define HEADS   16
#define HDIM    64
#define ATT_SCALE 0.125f   // power of two: exact in tf32

__device__ float g_qkv[SEQ_N * QKV_C];      // tf32-valued [n][3C]
__device__ float g_attn[SEQ_N * MODEL_C];   // tf32-valued [n][C]
__device__ float g_x[SEQ_N * MODEL_C];      // tf32(x)
__device__ float g_wq[QKV_C * MODEL_C];     // tf32(w_qkv)
__device__ float g_wp[MODEL_C * MODEL_C];   // tf32(w_proj)

// ---------------------------------------------------------------------------
__device__ __forceinline__ uint32_t f2tf32(float f) {
    uint32_t u;
    asm("cvt.rn.tf32.f32 %0, %1;" : "=r"(u) : "f"(f));
    return u;
}
__device__ __forceinline__ float rtf(float f) { return __uint_as_float(f2tf32(f)); }
// D += A*B  (m16n8k8, tf32 in, f32 accum)
__device__ __forceinline__ void mma8(float* d, const uint32_t* a, uint32_t b0, uint32_t b1) {
    asm volatile(
        "mma.sync.aligned.m16n8k8.row.col.f32.tf32.tf32.f32 "
        "{%0,%1,%2,%3}, {%4,%5,%6,%7}, {%8,%9}, {%0,%1,%2,%3};"
        : "+f"(d[0]), "+f"(d[1]), "+f"(d[2]), "+f"(d[3])
        : "r"(a[0]), "r"(a[1]), "r"(a[2]), "r"(a[3]), "r"(b0), "r"(b1));
}
__device__ __forceinline__ uint32_t smem_u32(const void* p) {
    return (uint32_t)__cvta_generic_to_shared(p);
}
__device__ __forceinline__ void cp16(uint32_t s, const void* g) {
    asm volatile("cp.async.cg.shared.global [%0], [%1], 16;" :: "r"(s), "l"(g));
}
#define CP_COMMIT() asm volatile("cp.async.commit_group;" ::: "memory")
#define CP_WAIT0()  asm volatile("cp.async.wait_group 0;" ::: "memory")
#define CP_WAIT1()  asm volatile("cp.async.wait_group 1;" ::: "memory")

// ===========================================================================
// Prologue: round fp32 arrays to tf32-valued fp32
// ===========================================================================
__global__ void __launch_bounds__(256)
cvt_tf32(const float* __restrict__ src, float* __restrict__ dst, int n4)
{
    int i = blockIdx.x * 256 + threadIdx.x;
    if (i < n4) {
        float4 v = ((const float4*)src)[i];
        v.x = rtf(v.x); v.y = rtf(v.y); v.z = rtf(v.z); v.w = rtf(v.w);
        ((float4*)dst)[i] = v;
    }
}

// ===========================================================================
// tf32 GEMM: C[M,Nc] = A[M,K] * B[Nc,K]^T (+bias). Inputs tf32-valued.
// 128 thr (4 warps, 2x2 grid of 64x64 tiles), BM=BN=128, BK=32.
// 3-stage cp.async ring, ONE __syncthreads per k-tile:
//   iter kt: wait(kt arrived) ; barrier ; issue(kt+2) ; mma(kt)
// issue(kt+2) overwrites stage (kt-1)%3, whose readers all passed the barrier.
// ===========================================================================
#define GP 36
#define GSTAGE (2 * 128 * GP)                 // words per stage (A then B)
#define GEMM_SMEM (3 * GSTAGE * 4)            // 110592 B -> 2 CTAs/SM

__global__ void __launch_bounds__(128, 2)
gemm_tf32(const float* __restrict__ A, const float* __restrict__ B,
          const float* __restrict__ bias, float* __restrict__ C,
          int M, int Nc, int K, int cvt_out)
{
    extern __shared__ float sg[];
    const int tid  = threadIdx.x;
    const int w    = tid >> 5;
    const int lane = tid & 31;
    const int g    = lane >> 2;
    const int tig  = lane & 3;
    const int bm = blockIdx.y * 128;
    const int bn = blockIdx.x * 128;
    const int wm = (w >> 1) * 64;
    const int wn = (w & 1) * 64;
    const uint32_t sbase = smem_u32(sg);

    float acc[4][8][4];
#pragma unroll
    for (int mi = 0; mi < 4; mi++)
#pragma unroll
        for (int ni = 0; ni < 8; ni++)
#pragma unroll
            for (int j = 0; j < 4; j++) acc[mi][ni][j] = 0.f;

    const int KT = K >> 5;

    auto issue = [&](int kt) {
        const int s = kt % 3;
        const float* Ab = A + (size_t)bm * K + kt * 32;
        const float* Bb = B + (size_t)bn * K + kt * 32;
        uint32_t sa = sbase + (uint32_t)(s * GSTAGE) * 4u;
        uint32_t sb = sa + (uint32_t)(128 * GP) * 4u;
#pragma unroll
        for (int p = 0; p < 8; p++) {
            int idx = tid + p * 128;        // 0..1023
            int r   = idx >> 3;             // 0..127
            int c4  = (idx & 7) << 2;       // 0,4,...,28
            cp16(sa + (uint32_t)(r * GP + c4) * 4u, Ab + (size_t)r * K + c4);
            cp16(sb + (uint32_t)(r * GP + c4) * 4u, Bb + (size_t)r * K + c4);
        }
        CP_COMMIT();
    };

    issue(0);
    issue(1);
    for (int kt = 0; kt < KT; kt++) {
        CP_WAIT1();          // group kt has landed (kt+1 may still be in flight)
        __syncthreads();     // all warps seeing it; all done reading stage (kt-1)%3
        if (kt + 2 < KT) issue(kt + 2);

        const uint32_t* As = (const uint32_t*)(sg + (kt % 3) * GSTAGE);
        const uint32_t* Bs = As + 128 * GP;
#pragma unroll
        for (int ks = 0; ks < 4; ks++) {
            const int kc = ks * 8 + tig;
            uint32_t af[4][4], bf[8][2];
#pragma unroll
            for (int mi = 0; mi < 4; mi++) {
                int r0 = wm + mi * 16;
                af[mi][0] = As[(r0 + g) * GP + kc];
                af[mi][1] = As[(r0 + g + 8) * GP + kc];
                af[mi][2] = As[(r0 + g) * GP + kc + 4];
                af[mi][3] = As[(r0 + g + 8) * GP + kc + 4];
            }
#pragma unroll
            for (int ni = 0; ni < 8; ni++) {
                int c0 = wn + ni * 8;
                bf[ni][0] = Bs[(c0 + g) * GP + kc];
                bf[ni][1] = Bs[(c0 + g) * GP + kc + 4];
            }
#pragma unroll
            for (int mi = 0; mi < 4; mi++)
#pragma unroll
                for (int ni = 0; ni < 8; ni++)
                    mma8(acc[mi][ni], af[mi], bf[ni][0], bf[ni][1]);
        }
    }

#pragma unroll
    for (int mi = 0; mi < 4; mi++) {
        int row = bm + wm + mi * 16 + g;
#pragma unroll
        for (int ni = 0; ni < 8; ni++) {
            int col = bn + wn + ni * 8 + 2 * tig;
            float2 b2 = bias ? *(const float2*)&bias[col] : make_float2(0.f, 0.f);
            float2 v0 = make_float2(acc[mi][ni][0] + b2.x, acc[mi][ni][1] + b2.y);
            float2 v1 = make_float2(acc[mi][ni][2] + b2.x, acc[mi][ni][3] + b2.y);
            if (cvt_out) {
                v0.x = rtf(v0.x); v0.y = rtf(v0.y);
                v1.x = rtf(v1.x); v1.y = rtf(v1.y);
            }
            *(float2*)&C[(size_t)row * Nc + col]       = v0;
            *(float2*)&C[(size_t)(row + 8) * Nc + col] = v1;
        }
    }
}

// ===========================================================================
// tf32 flash attention, key-permuted K staging (pi = [0,4,1,5,2,6,3,7]):
// S C-frag layout == P A-frag layout -> P feeds MMA2 from registers.
// K/V DOUBLE-BUFFERED across k-blocks: stage(kb+1) issued right after the
// barrier for kb, hidden under ~2048 cyc of MMAs. 1 CTA/SM (143KB smem).
// grid=(32,16), block=256 (8 warps x 16 q rows).
// ===========================================================================
#define KP 68
#define VP 72
#define STGW (128 * KP + 128 * VP)             // words per stage
#define ATT_SMEM (2 * STGW * 4)                // 143360 B

__global__ void __launch_bounds__(256, 1)
flash_mma(const float* __restrict__ qkv, float* __restrict__ out)
{
    extern __shared__ uint32_t su[];
    const int tid  = threadIdx.x;
    const int w    = tid >> 5;
    const int lane = tid & 31;
    const int g    = lane >> 2;
    const int tig  = lane & 3;
    const int qb   = (int)gridDim.x - 1 - (int)blockIdx.x;  // long CTAs first
    const int h    = blockIdx.y;
    const int qrow0 = qb * 128 + w * 16;
    const int r0g   = qrow0 + g;
    const uint32_t sb0 = smem_u32(su);

    // ---- Q fragments: tf32-valued in gmem; *0.125 exact ----
    uint32_t qf[8][4];
    {
        const float* qp = qkv + (size_t)qrow0 * QKV_C + h * HDIM;
#pragma unroll
        for (int ks = 0; ks < 8; ks++) {
            int c = ks * 8 + tig;
            qf[ks][0] = __float_as_uint(qp[(size_t)g * QKV_C + c] * ATT_SCALE);
            qf[ks][1] = __float_as_uint(qp[(size_t)(g + 8) * QKV_C + c] * ATT_SCALE);
            qf[ks][2] = __float_as_uint(qp[(size_t)g * QKV_C + c + 4] * ATT_SCALE);
            qf[ks][3] = __float_as_uint(qp[(size_t)(g + 8) * QKV_C + c + 4] * ATT_SCALE);
        }
    }

    float acc_o[8][4];
#pragma unroll
    for (int ni = 0; ni < 8; ni++)
#pragma unroll
        for (int j = 0; j < 4; j++) acc_o[ni][j] = 0.f;
    float l0 = 0.f, l1 = 0.f;

    const int sr  = tid >> 4;            // 0..15
    const int scl = (tid & 15) << 2;     // 0,4,...,60

    auto stage = [&](int kb, int s) {
        const uint32_t ksb = sb0 + (uint32_t)(s * STGW) * 4u;
        const uint32_t vsb = ksb + (uint32_t)(128 * KP) * 4u;
        const float* kp = qkv + (size_t)(kb * 128) * QKV_C + MODEL_C + h * HDIM;
#pragma unroll
        for (int p = 0; p < 8; p++) {
            int r = sr + p * 16;
            int rp = (r & ~7) | (((r & 3) << 1) | ((r & 7) >> 2));  // pi^-1
            cp16(ksb + (uint32_t)(rp * KP + scl) * 4u, kp + (size_t)r * QKV_C + scl);
            cp16(vsb + (uint32_t)(r * VP + scl) * 4u,
                 kp + (size_t)r * QKV_C + MODEL_C + scl);
        }
        CP_COMMIT();
    };

    stage(0, 0);
    for (int kb = 0; kb <= qb; kb++) {
        const int cur = kb & 1;
        CP_WAIT0();          // only {kb} in flight here
        __syncthreads();     // data visible to all; all done reading buf cur^1
        if (kb < qb) stage(kb + 1, cur ^ 1);   // overlaps with compute below

        const uint32_t* Ks = su + cur * STGW;
        const uint32_t* Vs = Ks + 128 * KP;

        const bool diag = (kb == qb);
        const int glim = diag ? (2 * w + 2) : 16;   // always even
#pragma unroll 2
        for (int grp = 0; grp < glim; grp++) {
            // ---- S n-tile: 8 keys, full D=64; two split chains ----
            float s4a[4] = {0.f, 0.f, 0.f, 0.f};
            float s4b[4] = {0.f, 0.f, 0.f, 0.f};
            const uint32_t* krow = &Ks[(grp * 8 + g) * KP];
#pragma unroll
            for (int ks = 0; ks < 4; ks++) {
                int kc0 = (2 * ks) * 8 + tig;
                int kc1 = (2 * ks + 1) * 8 + tig;
                mma8(s4a, qf[2 * ks],     krow[kc0], krow[kc0 + 4]);
                mma8(s4b, qf[2 * ks + 1], krow[kc1], krow[kc1 + 4]);
            }
            // ---- exp + causal mask (keys: p0/p2 -> +tig, p1/p3 -> +tig+4) ----
            float p0 = __expf(s4a[0] + s4b[0]);
            float p1 = __expf(s4a[1] + s4b[1]);
            float p2 = __expf(s4a[2] + s4b[2]);
            float p3 = __expf(s4a[3] + s4b[3]);
            if (diag) {
                int k0g = kb * 128 + grp * 8 + tig;
                if (k0g > r0g)         p0 = 0.f;
                if (k0g + 4 > r0g)     p1 = 0.f;
                if (k0g > r0g + 8)     p2 = 0.f;
                if (k0g + 4 > r0g + 8) p3 = 0.f;
            }
            l0 += p0 + p1;
            l1 += p2 + p3;
            // ---- P directly as A-fragment: {a0,a1,a2,a3} = {p0,p2,p1,p3} ----
            uint32_t af[4] = { f2tf32(p0), f2tf32(p2), f2tf32(p1), f2tf32(p3) };
            const uint32_t* vr0 = &Vs[(grp * 8 + tig) * VP];
            const uint32_t* vr1 = vr0 + 4 * VP;
#pragma unroll
            for (int ni = 0; ni < 8; ni++) {
                mma8(acc_o[ni], af, vr0[ni * 8 + g], vr1[ni * 8 + g]);
            }
        }
        __syncthreads();     // readers done before next iter's stage overwrite
    }

    // ---- finalize: quad-reduce l, normalize, store (tf32-rounded) ----
    l0 += __shfl_xor_sync(0xFFFFFFFFu, l0, 1);
    l0 += __shfl_xor_sync(0xFFFFFFFFu, l0, 2);
    l1 += __shfl_xor_sync(0xFFFFFFFFu, l1, 1);
    l1 += __shfl_xor_sync(0xFFFFFFFFu, l1, 2);
    const float inv0 = 1.f / l0;
    const float inv1 = 1.f / l1;

    float* dst0 = out + (size_t)(qrow0 + g) * MODEL_C + h * HDIM;
    float* dst1 = out + (size_t)(qrow0 + g + 8) * MODEL_C + h * HDIM;
#pragma unroll
    for (int ni = 0; ni < 8; ni++) {
        int col = ni * 8 + 2 * tig;
        *(float2*)&dst0[col] = make_float2(rtf(acc_o[ni][0] * inv0), rtf(acc_o[ni][1] * inv0));
        *(float2*)&dst1[col] = make_float2(rtf(acc_o[ni][2] * inv1), rtf(acc_o[ni][3] * inv1));
    }
}

// ===========================================================================
extern "C" void kernel_launch(void* const* d_in, const int* in_sizes, int n_in,
                              void* d_out, int out_size)
{
    const float* x      = (const float*)d_in[0];
    const float* w_qkv  = (const float*)d_in[1];
    const float* w_proj = (const float*)d_in[2];
    const float* b_proj = (const float*)d_in[3];
    float* out = (float*)d_out;

    float *qkv, *attn, *xt, *wq, *wp;
    cudaGetSymbolAddress((void**)&qkv,  g_qkv);
    cudaGetSymbolAddress((void**)&attn, g_attn);
    cudaGetSymbolAddress((void**)&xt,   g_x);
    cudaGetSymbolAddress((void**)&wq,   g_wq);
    cudaGetSymbolAddress((void**)&wp,   g_wp);

    cudaFuncSetAttribute(gemm_tf32, cudaFuncAttributeMaxDynamicSharedMemorySize, GEMM_SMEM);
    cudaFuncSetAttribute(flash_mma, cudaFuncAttributeMaxDynamicSharedMemorySize, ATT_SMEM);

    {   // prologue: tf32-round inputs
        int n4x = SEQ_N * MODEL_C / 4;
        int n4q = QKV_C * MODEL_C / 4;
        int n4p = MODEL_C * MODEL_C / 4;
        cvt_tf32<<<(n4x + 255) / 256, 256>>>(x, xt, n4x);
        cvt_tf32<<<(n4q + 255) / 256, 256>>>(w_qkv, wq, n4q);
        cvt_tf32<<<(n4p + 255) / 256, 256>>>(w_proj, wp, n4p);
    }
    {   // QKV projection (output tf32-rounded)
        dim3 grid(QKV_C / 128, SEQ_N / 128);
        gemm_tf32<<<grid, 128, GEMM_SMEM>>>(xt, wq, nullptr, qkv,
                                            SEQ_N, QKV_C, MODEL_C, 1);
    }
    {   // causal attention -> g_attn (tf32-rounded)
        dim3 grid(SEQ_N / 128, HEADS);
        flash_mma<<<grid, 256, ATT_SMEM>>>(qkv, attn);
    }
    {   // output projection + bias (fp32 out)
        dim3 grid(MODEL_C / 128, SEQ_N / 128);
        gemm_tf32<<<grid, 128, GEMM_SMEM>>>(attn, wp, b_proj, out,
                                            SEQ_N, MODEL_C, MODEL_C, 0);
    }
}

// round 16
// speedup vs baseline: 3.1372x; 1.8194x over previous
#include <cuda_runtime.h>
#include <cuda_fp16.h>
#include <math.h>
#include <stdint.h>

// ---------------------------------------------------------------------------
// Attention_9070970929715 on sm_103a — round 15: full fp16 mma.sync pipeline
// (m16n8k16, fp32 accumulate). fp16 = same 10-bit mantissa as tf32 but 2x
// MACs/instruction on the mma.sync path and half the memory traffic.
// ---------------------------------------------------------------------------

#define SEQ_N   4096
#define MODEL_C 1024
#define QKV_C   3072
#define HEADS   16
#define HDIM    64

__device__ __half g_qkv[SEQ_N * QKV_C];      // fp16 [n][3C]
__device__ __half g_attn[SEQ_N * MODEL_C];   // fp16 [n][C]
__device__ __half g_x[SEQ_N * MODEL_C];      // fp16(x)
__device__ __half g_wq[QKV_C * MODEL_C];     // fp16(w_qkv)
__device__ __half g_wp[MODEL_C * MODEL_C];   // fp16(w_proj)

// ---------------------------------------------------------------------------
__device__ __forceinline__ uint32_t h2pack(float a, float b) {
    __half2 h = __floats2half2_rn(a, b);
    return *(uint32_t*)&h;
}
// D += A*B  (m16n8k16, f16 in, f32 accum)
__device__ __forceinline__ void mma16(float* d, const uint32_t* a, uint32_t b0, uint32_t b1) {
    asm volatile(
        "mma.sync.aligned.m16n8k16.row.col.f32.f16.f16.f32 "
        "{%0,%1,%2,%3}, {%4,%5,%6,%7}, {%8,%9}, {%0,%1,%2,%3};"
        : "+f"(d[0]), "+f"(d[1]), "+f"(d[2]), "+f"(d[3])
        : "r"(a[0]), "r"(a[1]), "r"(a[2]), "r"(a[3]), "r"(b0), "r"(b1));
}
__device__ __forceinline__ void ldm4(uint32_t* r, uint32_t addr) {
    asm volatile("ldmatrix.sync.aligned.m8n8.x4.shared.b16 {%0,%1,%2,%3}, [%4];"
        : "=r"(r[0]), "=r"(r[1]), "=r"(r[2]), "=r"(r[3]) : "r"(addr));
}
__device__ __forceinline__ void ldm4t(uint32_t* r, uint32_t addr) {
    asm volatile("ldmatrix.sync.aligned.m8n8.x4.trans.shared.b16 {%0,%1,%2,%3}, [%4];"
        : "=r"(r[0]), "=r"(r[1]), "=r"(r[2]), "=r"(r[3]) : "r"(addr));
}
__device__ __forceinline__ uint32_t smem_u32(const void* p) {
    return (uint32_t)__cvta_generic_to_shared(p);
}
__device__ __forceinline__ void cp16(uint32_t s, const void* g) {
    asm volatile("cp.async.cg.shared.global [%0], [%1], 16;" :: "r"(s), "l"(g));
}
#define CP_COMMIT() asm volatile("cp.async.commit_group;" ::: "memory")
#define CP_WAIT0()  asm volatile("cp.async.wait_group 0;" ::: "memory")
#define CP_WAIT1()  asm volatile("cp.async.wait_group 1;" ::: "memory")

// ===========================================================================
// Prologue: fp32 -> fp16
// ===========================================================================
__global__ void __launch_bounds__(256)
cvt_f16(const float* __restrict__ src, __half* __restrict__ dst, int n4)
{
    int i = blockIdx.x * 256 + threadIdx.x;
    if (i < n4) {
        float4 v = ((const float4*)src)[i];
        uint2 o;
        o.x = h2pack(v.x, v.y);
        o.y = h2pack(v.z, v.w);
        ((uint2*)dst)[i] = o;
    }
}

// ===========================================================================
// fp16 GEMM: C[M,Nc] = A[M,K]*B[Nc,K]^T (+bias). 128 thr, 2x2 warps of 64x64.
// BM=BN=128, BK=32 halves; 3-stage cp.async ring, one barrier per tile.
// smem rows: 32 halves content, pitch 40 halves (20 words) — conflict-free.
// ===========================================================================
#define GPW 20                           // pitch in 4B words (= half2 units)
#define GMATW (128 * GPW)                // words per matrix
#define GSTW (2 * GMATW)                 // words per stage
#define GEMM_SMEM (3 * GSTW * 4)         // 61440 B

__global__ void __launch_bounds__(128, 2)
gemm_f16(const __half* __restrict__ A, const __half* __restrict__ B,
         const float* __restrict__ bias, void* __restrict__ Cv,
         int M, int Nc, int K, int out_half)
{
    extern __shared__ uint32_t sg[];
    const int tid  = threadIdx.x;
    const int w    = tid >> 5;
    const int lane = tid & 31;
    const int g    = lane >> 2;
    const int tig  = lane & 3;
    const int bm = blockIdx.y * 128;
    const int bn = blockIdx.x * 128;
    const int wm = (w >> 1) * 64;
    const int wn = (w & 1) * 64;
    const uint32_t sbase = smem_u32(sg);

    float acc[4][8][4];
#pragma unroll
    for (int mi = 0; mi < 4; mi++)
#pragma unroll
        for (int ni = 0; ni < 8; ni++)
#pragma unroll
            for (int j = 0; j < 4; j++) acc[mi][ni][j] = 0.f;

    const int KT = K >> 5;

    auto issue = [&](int kt) {
        const int s = kt % 3;
        const __half* Ab = A + (size_t)bm * K + kt * 32;
        const __half* Bb = B + (size_t)bn * K + kt * 32;
        uint32_t sa = sbase + (uint32_t)(s * GSTW) * 4u;
        uint32_t sb = sa + (uint32_t)GMATW * 4u;
#pragma unroll
        for (int p = 0; p < 4; p++) {               // A: 512 chunks of 16B
            int idx = tid + p * 128;                // 0..511
            int r = idx >> 2;                       // 0..127
            int c = (idx & 3) * 8;                  // halves 0,8,16,24
            cp16(sa + (uint32_t)(r * GPW + c / 2) * 4u, Ab + (size_t)r * K + c);
        }
#pragma unroll
        for (int p = 0; p < 4; p++) {               // B
            int idx = tid + p * 128;
            int r = idx >> 2;
            int c = (idx & 3) * 8;
            cp16(sb + (uint32_t)(r * GPW + c / 2) * 4u, Bb + (size_t)r * K + c);
        }
        CP_COMMIT();
    };

    issue(0);
    issue(1);
    for (int kt = 0; kt < KT; kt++) {
        CP_WAIT1();
        __syncthreads();
        if (kt + 2 < KT) issue(kt + 2);

        const uint32_t* As = sg + (kt % 3) * GSTW;
        const uint32_t* Bs = As + GMATW;
#pragma unroll
        for (int ks = 0; ks < 2; ks++) {            // two k16 steps per BK=32
            const int kc = ks * 8 + tig;            // half2 index in row
            uint32_t af[4][4], bf[8][2];
#pragma unroll
            for (int mi = 0; mi < 4; mi++) {
                int r0 = wm + mi * 16;
                af[mi][0] = As[(r0 + g) * GPW + kc];
                af[mi][1] = As[(r0 + g + 8) * GPW + kc];
                af[mi][2] = As[(r0 + g) * GPW + kc + 4];
                af[mi][3] = As[(r0 + g + 8) * GPW + kc + 4];
            }
#pragma unroll
            for (int ni = 0; ni < 8; ni++) {
                int c0 = wn + ni * 8;
                bf[ni][0] = Bs[(c0 + g) * GPW + kc];
                bf[ni][1] = Bs[(c0 + g) * GPW + kc + 4];
            }
#pragma unroll
            for (int mi = 0; mi < 4; mi++)
#pragma unroll
                for (int ni = 0; ni < 8; ni++)
                    mma16(acc[mi][ni], af[mi], bf[ni][0], bf[ni][1]);
        }
    }

#pragma unroll
    for (int mi = 0; mi < 4; mi++) {
        int row = bm + wm + mi * 16 + g;
#pragma unroll
        for (int ni = 0; ni < 8; ni++) {
            int col = bn + wn + ni * 8 + 2 * tig;
            if (out_half) {
                __half* Ch = (__half*)Cv;
                *(uint32_t*)&Ch[(size_t)row * Nc + col] =
                    h2pack(acc[mi][ni][0], acc[mi][ni][1]);
                *(uint32_t*)&Ch[(size_t)(row + 8) * Nc + col] =
                    h2pack(acc[mi][ni][2], acc[mi][ni][3]);
            } else {
                float* Cf = (float*)Cv;
                float2 b2 = bias ? *(const float2*)&bias[col] : make_float2(0.f, 0.f);
                *(float2*)&Cf[(size_t)row * Nc + col] =
                    make_float2(acc[mi][ni][0] + b2.x, acc[mi][ni][1] + b2.y);
                *(float2*)&Cf[(size_t)(row + 8) * Nc + col] =
                    make_float2(acc[mi][ni][2] + b2.x, acc[mi][ni][3] + b2.y);
            }
        }
    }
}

// ===========================================================================
// fp16 flash attention. grid=(32,16), block=256 (8 warps x 16 q rows).
// S via m16n8k16 (A=Q regs, B=K via ldmatrix); S C-frag keys {2tig,2tig+1}
// pack DIRECTLY into P A-frag half2s (no permutation needed in fp16).
// P*V via m16n8k16 with B = V through ldmatrix.trans on natural [key][d].
// K/V tiles: 144B-pitch rows (conflict-free ldmatrix), cp.async staged,
// double-buffered across k-blocks. 2 CTAs/SM.
// ===========================================================================
#define FPW 36                             // row pitch in words (72 halves)
#define FMATW (128 * FPW)                  // 4608 words per matrix
#define FSTW (2 * FMATW)                   // 9216 words per stage (K then V)
#define ATT_SMEM (2 * FSTW * 4)            // 73728 B

__global__ void __launch_bounds__(256, 2)
flash_f16(const __half* __restrict__ qkv, __half* __restrict__ out)
{
    extern __shared__ uint32_t su[];
    const int tid  = threadIdx.x;
    const int w    = tid >> 5;
    const int lane = tid & 31;
    const int g    = lane >> 2;
    const int tig  = lane & 3;
    const int qb   = (int)gridDim.x - 1 - (int)blockIdx.x;  // long CTAs first
    const int h    = blockIdx.y;
    const int qrow0 = qb * 128 + w * 16;
    const int r0g   = qrow0 + g;
    const uint32_t sb0 = smem_u32(su);

    // ldmatrix per-lane base offsets (bytes)
    // K (non-trans): matrix m=l>>3: keys (m>>1)*8 + (l&7), d-chunk (m&1)*8
    const uint32_t lbk = (uint32_t)(((((lane >> 4) * 8) + (lane & 7)) * FPW
                                     + ((lane >> 3) & 1) * 4) * 4);
    // V (trans): matrix m: keys (m&1)*8 + (l&7), d-chunk (m>>1)*8
    const uint32_t lbv = (uint32_t)((((((lane >> 3) & 1) * 8) + (lane & 7)) * FPW
                                     + (lane >> 4) * 4) * 4);

    // ---- Q fragments: 4 k16-steps over D=64; scale 0.125 exact in fp16 ----
    uint32_t qf[4][4];
    {
        const __half* qp = qkv + (size_t)qrow0 * QKV_C + h * HDIM;
        const __half2 sc = __floats2half2_rn(0.125f, 0.125f);
#pragma unroll
        for (int ks = 0; ks < 4; ks++) {
            int c = ks * 16 + 2 * tig;
            __half2 v0 = __hmul2(*(const __half2*)(qp + (size_t)g * QKV_C + c), sc);
            __half2 v1 = __hmul2(*(const __half2*)(qp + (size_t)(g + 8) * QKV_C + c), sc);
            __half2 v2 = __hmul2(*(const __half2*)(qp + (size_t)g * QKV_C + c + 8), sc);
            __half2 v3 = __hmul2(*(const __half2*)(qp + (size_t)(g + 8) * QKV_C + c + 8), sc);
            qf[ks][0] = *(uint32_t*)&v0;
            qf[ks][1] = *(uint32_t*)&v1;
            qf[ks][2] = *(uint32_t*)&v2;
            qf[ks][3] = *(uint32_t*)&v3;
        }
    }

    float acc_o[8][4];
#pragma unroll
    for (int ni = 0; ni < 8; ni++)
#pragma unroll
        for (int j = 0; j < 4; j++) acc_o[ni][j] = 0.f;
    float l0 = 0.f, l1 = 0.f;

    auto stage = [&](int kb, int s) {
        uint32_t kw = sb0 + (uint32_t)(s * FSTW) * 4u;
        uint32_t vw = kw + (uint32_t)FMATW * 4u;
        const __half* kp = qkv + (size_t)(kb * 128) * QKV_C + MODEL_C + h * HDIM;
#pragma unroll
        for (int p = 0; p < 4; p++) {               // K: 1024 chunks of 16B
            int idx = tid + p * 256;
            int r = idx >> 3;
            int c = (idx & 7) * 8;                  // halves
            cp16(kw + (uint32_t)(r * FPW + c / 2) * 4u, kp + (size_t)r * QKV_C + c);
        }
#pragma unroll
        for (int p = 0; p < 4; p++) {               // V
            int idx = tid + p * 256;
            int r = idx >> 3;
            int c = (idx & 7) * 8;
            cp16(vw + (uint32_t)(r * FPW + c / 2) * 4u,
                 kp + (size_t)r * QKV_C + MODEL_C + c);
        }
        CP_COMMIT();
    };

    stage(0, 0);
    for (int kb = 0; kb <= qb; kb++) {
        const int cur = kb & 1;
        CP_WAIT0();
        __syncthreads();
        if (kb < qb) stage(kb + 1, cur ^ 1);   // overlaps compute below

        const uint32_t kwb = sb0 + (uint32_t)(cur * FSTW) * 4u;
        const uint32_t vwb = kwb + (uint32_t)FMATW * 4u;

        const bool diag = (kb == qb);
        const int glim = diag ? (w + 1) : 8;    // 16-key groups
        for (int grp = 0; grp < glim; grp++) {
            const uint32_t goff = (uint32_t)(grp * 16 * FPW) * 4u;
            // ---- S: two 8-key n-tiles, 4 k16 steps over D=64 ----
            float s0[4] = {0.f, 0.f, 0.f, 0.f};
            float s1[4] = {0.f, 0.f, 0.f, 0.f};
#pragma unroll
            for (int ks = 0; ks < 4; ks++) {
                uint32_t kr[4];
                ldm4(kr, kwb + goff + lbk + (uint32_t)(ks * 8) * 4u);
                mma16(s0, qf[ks], kr[0], kr[1]);   // keys grp*16+0..7
                mma16(s1, qf[ks], kr[2], kr[3]);   // keys grp*16+8..15
            }
            // ---- exp + causal mask ----
            float p00 = __expf(s0[0]), p01 = __expf(s0[1]);
            float p02 = __expf(s0[2]), p03 = __expf(s0[3]);
            float p10 = __expf(s1[0]), p11 = __expf(s1[1]);
            float p12 = __expf(s1[2]), p13 = __expf(s1[3]);
            if (diag) {
                int k0 = kb * 128 + grp * 16 + 2 * tig;   // keys k0,k0+1,k0+8,k0+9
                if (k0 > r0g)         p00 = 0.f;
                if (k0 + 1 > r0g)     p01 = 0.f;
                if (k0 + 8 > r0g)     p10 = 0.f;
                if (k0 + 9 > r0g)     p11 = 0.f;
                if (k0 > r0g + 8)     p02 = 0.f;
                if (k0 + 1 > r0g + 8) p03 = 0.f;
                if (k0 + 8 > r0g + 8) p12 = 0.f;
                if (k0 + 9 > r0g + 8) p13 = 0.f;
            }
            l0 += p00 + p01 + p10 + p11;
            l1 += p02 + p03 + p12 + p13;
            // ---- P as A-frag: direct half2 packing ----
            uint32_t af[4] = { h2pack(p00, p01), h2pack(p02, p03),
                               h2pack(p10, p11), h2pack(p12, p13) };
            // ---- O += P*V : 8 d-tiles, K=16 keys (this group) ----
#pragma unroll
            for (int dc = 0; dc < 4; dc++) {
                uint32_t vr[4];
                ldm4t(vr, vwb + goff + lbv + (uint32_t)(dc * 8) * 4u);
                mma16(acc_o[2 * dc],     af, vr[0], vr[1]);
                mma16(acc_o[2 * dc + 1], af, vr[2], vr[3]);
            }
        }
        __syncthreads();   // readers done before next stage overwrite
    }

    // ---- finalize: quad-reduce l, normalize, store fp16 ----
    l0 += __shfl_xor_sync(0xFFFFFFFFu, l0, 1);
    l0 += __shfl_xor_sync(0xFFFFFFFFu, l0, 2);
    l1 += __shfl_xor_sync(0xFFFFFFFFu, l1, 1);
    l1 += __shfl_xor_sync(0xFFFFFFFFu, l1, 2);
    const float inv0 = 1.f / l0;
    const float inv1 = 1.f / l1;

    __half* dst0 = out + (size_t)(qrow0 + g) * MODEL_C + h * HDIM;
    __half* dst1 = out + (size_t)(qrow0 + g + 8) * MODEL_C + h * HDIM;
#pragma unroll
    for (int ni = 0; ni < 8; ni++) {
        int col = ni * 8 + 2 * tig;
        *(uint32_t*)&dst0[col] = h2pack(acc_o[ni][0] * inv0, acc_o[ni][1] * inv0);
        *(uint32_t*)&dst1[col] = h2pack(acc_o[ni][2] * inv1, acc_o[ni][3] * inv1);
    }
}

// ===========================================================================
extern "C" void kernel_launch(void* const* d_in, const int* in_sizes, int n_in,
                              void* d_out, int out_size)
{
    const float* x      = (const float*)d_in[0];
    const float* w_qkv  = (const float*)d_in[1];
    const float* w_proj = (const float*)d_in[2];
    const float* b_proj = (const float*)d_in[3];
    float* out = (float*)d_out;

    __half *qkv, *attn, *xt, *wq, *wp;
    cudaGetSymbolAddress((void**)&qkv,  g_qkv);
    cudaGetSymbolAddress((void**)&attn, g_attn);
    cudaGetSymbolAddress((void**)&xt,   g_x);
    cudaGetSymbolAddress((void**)&wq,   g_wq);
    cudaGetSymbolAddress((void**)&wp,   g_wp);

    cudaFuncSetAttribute(gemm_f16,  cudaFuncAttributeMaxDynamicSharedMemorySize, GEMM_SMEM);
    cudaFuncSetAttribute(flash_f16, cudaFuncAttributeMaxDynamicSharedMemorySize, ATT_SMEM);

    {   // prologue: fp32 -> fp16
        int n4x = SEQ_N * MODEL_C / 4;
        int n4q = QKV_C * MODEL_C / 4;
        int n4p = MODEL_C * MODEL_C / 4;
        cvt_f16<<<(n4x + 255) / 256, 256>>>(x, xt, n4x);
        cvt_f16<<<(n4q + 255) / 256, 256>>>(w_qkv, wq, n4q);
        cvt_f16<<<(n4p + 255) / 256, 256>>>(w_proj, wp, n4p);
    }
    {   // QKV projection -> fp16 scratch
        dim3 grid(QKV_C / 128, SEQ_N / 128);
        gemm_f16<<<grid, 128, GEMM_SMEM>>>(xt, wq, nullptr, qkv,
                                           SEQ_N, QKV_C, MODEL_C, 1);
    }
    {   // causal attention -> fp16 scratch
        dim3 grid(SEQ_N / 128, HEADS);
        flash_f16<<<grid, 256, ATT_SMEM>>>(qkv, attn);
    }
    {   // output projection + bias -> fp32 out
        dim3 grid(MODEL_C / 128, SEQ_N / 128);
        gemm_f16<<<grid, 128, GEMM_SMEM>>>(attn, wp, b_proj, out,
                                           SEQ_N, MODEL_C, MODEL_C, 0);
    }
}

// round 17
// speedup vs baseline: 3.4461x; 1.0985x over previous
#include <cuda_runtime.h>
#include <cuda_fp16.h>
#include <math.h>
#include <stdint.h>

// ---------------------------------------------------------------------------
// Attention_9070970929715 on sm_103a — round 17: fp16 mma.sync pipeline
// GEMM fragment loads via ldmatrix.x4; flash on 64-row q-tiles for balance;
// fused fp32->fp16 prologue.
// ---------------------------------------------------------------------------

#define SEQ_N   4096
#define MODEL_C 1024
#define QKV_C   3072
#define HEADS   16
#define HDIM    64

__device__ __half g_qkv[SEQ_N * QKV_C];      // fp16 [n][3C]
__device__ __half g_attn[SEQ_N * MODEL_C];   // fp16 [n][C]
__device__ __half g_x[SEQ_N * MODEL_C];
__device__ __half g_wq[QKV_C * MODEL_C];
__device__ __half g_wp[MODEL_C * MODEL_C];

// ---------------------------------------------------------------------------
__device__ __forceinline__ uint32_t h2pack(float a, float b) {
    __half2 h = __floats2half2_rn(a, b);
    return *(uint32_t*)&h;
}
__device__ __forceinline__ void mma16(float* d, const uint32_t* a, uint32_t b0, uint32_t b1) {
    asm volatile(
        "mma.sync.aligned.m16n8k16.row.col.f32.f16.f16.f32 "
        "{%0,%1,%2,%3}, {%4,%5,%6,%7}, {%8,%9}, {%0,%1,%2,%3};"
        : "+f"(d[0]), "+f"(d[1]), "+f"(d[2]), "+f"(d[3])
        : "r"(a[0]), "r"(a[1]), "r"(a[2]), "r"(a[3]), "r"(b0), "r"(b1));
}
__device__ __forceinline__ void ldm4(uint32_t* r, uint32_t addr) {
    asm volatile("ldmatrix.sync.aligned.m8n8.x4.shared.b16 {%0,%1,%2,%3}, [%4];"
        : "=r"(r[0]), "=r"(r[1]), "=r"(r[2]), "=r"(r[3]) : "r"(addr));
}
__device__ __forceinline__ void ldm4t(uint32_t* r, uint32_t addr) {
    asm volatile("ldmatrix.sync.aligned.m8n8.x4.trans.shared.b16 {%0,%1,%2,%3}, [%4];"
        : "=r"(r[0]), "=r"(r[1]), "=r"(r[2]), "=r"(r[3]) : "r"(addr));
}
__device__ __forceinline__ uint32_t smem_u32(const void* p) {
    return (uint32_t)__cvta_generic_to_shared(p);
}
__device__ __forceinline__ void cp16(uint32_t s, const void* g) {
    asm volatile("cp.async.cg.shared.global [%0], [%1], 16;" :: "r"(s), "l"(g));
}
#define CP_COMMIT() asm volatile("cp.async.commit_group;" ::: "memory")
#define CP_WAIT0()  asm volatile("cp.async.wait_group 0;" ::: "memory")
#define CP_WAIT1()  asm volatile("cp.async.wait_group 1;" ::: "memory")

// ===========================================================================
// Fused prologue: three fp32 arrays -> fp16
// ===========================================================================
#define N4X (SEQ_N * MODEL_C / 4)
#define N4Q (QKV_C * MODEL_C / 4)
#define N4P (MODEL_C * MODEL_C / 4)

__global__ void __launch_bounds__(256)
cvt_all(const float* __restrict__ x, const float* __restrict__ wq,
        const float* __restrict__ wp, __half* __restrict__ dx,
        __half* __restrict__ dwq, __half* __restrict__ dwp)
{
    int i = blockIdx.x * 256 + threadIdx.x;
    const float* s;
    __half* d;
    int j;
    if (i < N4X)                { s = x;  d = dx;  j = i; }
    else if (i < N4X + N4Q)     { s = wq; d = dwq; j = i - N4X; }
    else if (i < N4X + N4Q+N4P) { s = wp; d = dwp; j = i - N4X - N4Q; }
    else return;
    float4 v = ((const float4*)s)[j];
    uint2 o;
    o.x = h2pack(v.x, v.y);
    o.y = h2pack(v.z, v.w);
    ((uint2*)d)[j] = o;
}

// ===========================================================================
// fp16 GEMM: C[M,Nc] = A[M,K]*B[Nc,K]^T (+bias). 128 thr, 2x2 warps of 64x64.
// BK=32; 3-stage cp.async ring, one barrier per tile; ldmatrix.x4 frags.
// ===========================================================================
#define GPW 20                           // row pitch in 4B words (40 halves)
#define GMATW (128 * GPW)
#define GSTW (2 * GMATW)
#define GEMM_SMEM (3 * GSTW * 4)         // 61440 B

__global__ void __launch_bounds__(128, 2)
gemm_f16(const __half* __restrict__ A, const __half* __restrict__ B,
         const float* __restrict__ bias, void* __restrict__ Cv,
         int M, int Nc, int K, int out_half)
{
    extern __shared__ uint32_t sg[];
    const int tid  = threadIdx.x;
    const int w    = tid >> 5;
    const int lane = tid & 31;
    const int g    = lane >> 2;
    const int tig  = lane & 3;
    const int bm = blockIdx.y * 128;
    const int bn = blockIdx.x * 128;
    const int wm = (w >> 1) * 64;
    const int wn = (w & 1) * 64;
    const uint32_t sbase = smem_u32(sg);

    // ldmatrix lane offsets (bytes): A rows0-7/8-15 x klo/khi; B n-octets x klo/khi
    const uint32_t laneA = (uint32_t)((((lane & 7) + ((lane >> 3) & 1) * 8) * GPW
                                       + (lane >> 4) * 4) * 4);
    const uint32_t laneB = (uint32_t)((((lane & 7) + (lane >> 4) * 8) * GPW
                                       + ((lane >> 3) & 1) * 4) * 4);

    float acc[4][8][4];
#pragma unroll
    for (int mi = 0; mi < 4; mi++)
#pragma unroll
        for (int ni = 0; ni < 8; ni++)
#pragma unroll
            for (int j = 0; j < 4; j++) acc[mi][ni][j] = 0.f;

    const int KT = K >> 5;

    auto issue = [&](int kt) {
        const int s = kt % 3;
        const __half* Ab = A + (size_t)bm * K + kt * 32;
        const __half* Bb = B + (size_t)bn * K + kt * 32;
        uint32_t sa = sbase + (uint32_t)(s * GSTW) * 4u;
        uint32_t sb = sa + (uint32_t)GMATW * 4u;
#pragma unroll
        for (int p = 0; p < 4; p++) {
            int idx = tid + p * 128;
            int r = idx >> 2;
            int c = (idx & 3) * 8;
            cp16(sa + (uint32_t)(r * GPW + c / 2) * 4u, Ab + (size_t)r * K + c);
        }
#pragma unroll
        for (int p = 0; p < 4; p++) {
            int idx = tid + p * 128;
            int r = idx >> 2;
            int c = (idx & 3) * 8;
            cp16(sb + (uint32_t)(r * GPW + c / 2) * 4u, Bb + (size_t)r * K + c);
        }
        CP_COMMIT();
    };

    issue(0);
    issue(1);
    for (int kt = 0; kt < KT; kt++) {
        CP_WAIT1();
        __syncthreads();
        if (kt + 2 < KT) issue(kt + 2);

        const uint32_t sa = sbase + (uint32_t)((kt % 3) * GSTW) * 4u;
        const uint32_t sb = sa + (uint32_t)GMATW * 4u;
#pragma unroll
        for (int ks = 0; ks < 2; ks++) {
            const uint32_t ko = (uint32_t)(ks * 8) * 4u;
            uint32_t af[4][4], bf[4][4];
#pragma unroll
            for (int mi = 0; mi < 4; mi++)
                ldm4(af[mi], sa + (uint32_t)((wm + mi * 16) * GPW) * 4u + ko + laneA);
#pragma unroll
            for (int np = 0; np < 4; np++)
                ldm4(bf[np], sb + (uint32_t)((wn + np * 16) * GPW) * 4u + ko + laneB);
#pragma unroll
            for (int mi = 0; mi < 4; mi++)
#pragma unroll
                for (int np = 0; np < 4; np++) {
                    mma16(acc[mi][2 * np],     af[mi], bf[np][0], bf[np][1]);
                    mma16(acc[mi][2 * np + 1], af[mi], bf[np][2], bf[np][3]);
                }
        }
    }

#pragma unroll
    for (int mi = 0; mi < 4; mi++) {
        int row = bm + wm + mi * 16 + g;
#pragma unroll
        for (int ni = 0; ni < 8; ni++) {
            int col = bn + wn + ni * 8 + 2 * tig;
            if (out_half) {
                __half* Ch = (__half*)Cv;
                *(uint32_t*)&Ch[(size_t)row * Nc + col] =
                    h2pack(acc[mi][ni][0], acc[mi][ni][1]);
                *(uint32_t*)&Ch[(size_t)(row + 8) * Nc + col] =
                    h2pack(acc[mi][ni][2], acc[mi][ni][3]);
            } else {
                float* Cf = (float*)Cv;
                float2 b2 = bias ? *(const float2*)&bias[col] : make_float2(0.f, 0.f);
                *(float2*)&Cf[(size_t)row * Nc + col] =
                    make_float2(acc[mi][ni][0] + b2.x, acc[mi][ni][1] + b2.y);
                *(float2*)&Cf[(size_t)(row + 8) * Nc + col] =
                    make_float2(acc[mi][ni][2] + b2.x, acc[mi][ni][3] + b2.y);
            }
        }
    }
}

// ===========================================================================
// fp16 flash attention, 64-row q-tiles. grid=(64,16), block=128 (4 warps).
// Warp w owns q rows qt*64 + w*16 ..+16. K/V (128 keys) staged per k-block,
// double-buffered. S: A=Q regs, B=K ldmatrix; P packs straight into A-frags;
// PV: B=V ldmatrix.trans. 2 CTAs/SM; long-tiles-first.
// ===========================================================================
#define FPW 36                             // row pitch words (72 halves)
#define FMATW (128 * FPW)
#define FSTW (2 * FMATW)
#define ATT_SMEM (2 * FSTW * 4)            // 73728 B

__global__ void __launch_bounds__(128, 2)
flash_f16(const __half* __restrict__ qkv, __half* __restrict__ out)
{
    extern __shared__ uint32_t su[];
    const int tid  = threadIdx.x;
    const int w    = tid >> 5;
    const int lane = tid & 31;
    const int g    = lane >> 2;
    const int tig  = lane & 3;
    const int qt   = (int)gridDim.x - 1 - (int)blockIdx.x;  // long first
    const int h    = blockIdx.y;
    const int qrow0 = qt * 64 + w * 16;
    const int r0g   = qrow0 + g;
    const uint32_t sb0 = smem_u32(su);

    const uint32_t lbk = (uint32_t)(((((lane >> 4) * 8) + (lane & 7)) * FPW
                                     + ((lane >> 3) & 1) * 4) * 4);
    const uint32_t lbv = (uint32_t)((((((lane >> 3) & 1) * 8) + (lane & 7)) * FPW
                                     + (lane >> 4) * 4) * 4);

    // ---- Q fragments ----
    uint32_t qf[4][4];
    {
        const __half* qp = qkv + (size_t)qrow0 * QKV_C + h * HDIM;
        const __half2 sc = __floats2half2_rn(0.125f, 0.125f);
#pragma unroll
        for (int ks = 0; ks < 4; ks++) {
            int c = ks * 16 + 2 * tig;
            __half2 v0 = __hmul2(*(const __half2*)(qp + (size_t)g * QKV_C + c), sc);
            __half2 v1 = __hmul2(*(const __half2*)(qp + (size_t)(g + 8) * QKV_C + c), sc);
            __half2 v2 = __hmul2(*(const __half2*)(qp + (size_t)g * QKV_C + c + 8), sc);
            __half2 v3 = __hmul2(*(const __half2*)(qp + (size_t)(g + 8) * QKV_C + c + 8), sc);
            qf[ks][0] = *(uint32_t*)&v0;
            qf[ks][1] = *(uint32_t*)&v1;
            qf[ks][2] = *(uint32_t*)&v2;
            qf[ks][3] = *(uint32_t*)&v3;
        }
    }

    float acc_o[8][4];
#pragma unroll
    for (int ni = 0; ni < 8; ni++)
#pragma unroll
        for (int j = 0; j < 4; j++) acc_o[ni][j] = 0.f;
    float l0 = 0.f, l1 = 0.f;

    auto stage = [&](int kb, int s) {
        uint32_t kw = sb0 + (uint32_t)(s * FSTW) * 4u;
        uint32_t vw = kw + (uint32_t)FMATW * 4u;
        const __half* kp = qkv + (size_t)(kb * 128) * QKV_C + MODEL_C + h * HDIM;
#pragma unroll
        for (int p = 0; p < 8; p++) {
            int idx = tid + p * 128;
            int r = idx >> 3;
            int c = (idx & 7) * 8;
            cp16(kw + (uint32_t)(r * FPW + c / 2) * 4u, kp + (size_t)r * QKV_C + c);
        }
#pragma unroll
        for (int p = 0; p < 8; p++) {
            int idx = tid + p * 128;
            int r = idx >> 3;
            int c = (idx & 7) * 8;
            cp16(vw + (uint32_t)(r * FPW + c / 2) * 4u,
                 kp + (size_t)r * QKV_C + MODEL_C + c);
        }
        CP_COMMIT();
    };

    const int kbmax = qt >> 1;
    stage(0, 0);
    for (int kb = 0; kb <= kbmax; kb++) {
        const int cur = kb & 1;
        CP_WAIT0();
        __syncthreads();
        if (kb < kbmax) stage(kb + 1, cur ^ 1);

        const uint32_t kwb = sb0 + (uint32_t)(cur * FSTW) * 4u;
        const uint32_t vwb = kwb + (uint32_t)FMATW * 4u;

        const bool diag = (kb == kbmax);
        const int glim = diag ? ((qt & 1) * 4 + w + 1) : 8;
        for (int grp = 0; grp < glim; grp++) {
            const uint32_t goff = (uint32_t)(grp * 16 * FPW) * 4u;
            float s0[4] = {0.f, 0.f, 0.f, 0.f};
            float s1[4] = {0.f, 0.f, 0.f, 0.f};
#pragma unroll
            for (int ks = 0; ks < 4; ks++) {
                uint32_t kr[4];
                ldm4(kr, kwb + goff + lbk + (uint32_t)(ks * 8) * 4u);
                mma16(s0, qf[ks], kr[0], kr[1]);
                mma16(s1, qf[ks], kr[2], kr[3]);
            }
            float p00 = __expf(s0[0]), p01 = __expf(s0[1]);
            float p02 = __expf(s0[2]), p03 = __expf(s0[3]);
            float p10 = __expf(s1[0]), p11 = __expf(s1[1]);
            float p12 = __expf(s1[2]), p13 = __expf(s1[3]);
            if (diag) {
                int k0 = kb * 128 + grp * 16 + 2 * tig;
                if (k0 > r0g)         p00 = 0.f;
                if (k0 + 1 > r0g)     p01 = 0.f;
                if (k0 + 8 > r0g)     p10 = 0.f;
                if (k0 + 9 > r0g)     p11 = 0.f;
                if (k0 > r0g + 8)     p02 = 0.f;
                if (k0 + 1 > r0g + 8) p03 = 0.f;
                if (k0 + 8 > r0g + 8) p12 = 0.f;
                if (k0 + 9 > r0g + 8) p13 = 0.f;
            }
            l0 += p00 + p01 + p10 + p11;
            l1 += p02 + p03 + p12 + p13;
            uint32_t af[4] = { h2pack(p00, p01), h2pack(p02, p03),
                               h2pack(p10, p11), h2pack(p12, p13) };
#pragma unroll
            for (int dc = 0; dc < 4; dc++) {
                uint32_t vr[4];
                ldm4t(vr, vwb + goff + lbv + (uint32_t)(dc * 8) * 4u);
                mma16(acc_o[2 * dc],     af, vr[0], vr[1]);
                mma16(acc_o[2 * dc + 1], af, vr[2], vr[3]);
            }
        }
        __syncthreads();
    }

    // ---- finalize ----
    l0 += __shfl_xor_sync(0xFFFFFFFFu, l0, 1);
    l0 += __shfl_xor_sync(0xFFFFFFFFu, l0, 2);
    l1 += __shfl_xor_sync(0xFFFFFFFFu, l1, 1);
    l1 += __shfl_xor_sync(0xFFFFFFFFu, l1, 2);
    const float inv0 = 1.f / l0;
    const float inv1 = 1.f / l1;

    __half* dst0 = out + (size_t)(qrow0 + g) * MODEL_C + h * HDIM;
    __half* dst1 = out + (size_t)(qrow0 + g + 8) * MODEL_C + h * HDIM;
#pragma unroll
    for (int ni = 0; ni < 8; ni++) {
        int col = ni * 8 + 2 * tig;
        *(uint32_t*)&dst0[col] = h2pack(acc_o[ni][0] * inv0, acc_o[ni][1] * inv0);
        *(uint32_t*)&dst1[col] = h2pack(acc_o[ni][2] * inv1, acc_o[ni][3] * inv1);
    }
}

// ===========================================================================
extern "C" void kernel_launch(void* const* d_in, const int* in_sizes, int n_in,
                              void* d_out, int out_size)
{
    const float* x      = (const float*)d_in[0];
    const float* w_qkv  = (const float*)d_in[1];
    const float* w_proj = (const float*)d_in[2];
    const float* b_proj = (const float*)d_in[3];
    float* out = (float*)d_out;

    __half *qkv, *attn, *xt, *wq, *wp;
    cudaGetSymbolAddress((void**)&qkv,  g_qkv);
    cudaGetSymbolAddress((void**)&attn, g_attn);
    cudaGetSymbolAddress((void**)&xt,   g_x);
    cudaGetSymbolAddress((void**)&wq,   g_wq);
    cudaGetSymbolAddress((void**)&wp,   g_wp);

    cudaFuncSetAttribute(gemm_f16,  cudaFuncAttributeMaxDynamicSharedMemorySize, GEMM_SMEM);
    cudaFuncSetAttribute(flash_f16, cudaFuncAttributeMaxDynamicSharedMemorySize, ATT_SMEM);

    {   // fused prologue: fp32 -> fp16 (x, w_qkv, w_proj)
        int total4 = N4X + N4Q + N4P;
        cvt_all<<<(total4 + 255) / 256, 256>>>(x, w_qkv, w_proj, xt, wq, wp);
    }
    {   // QKV projection -> fp16 scratch
        dim3 grid(QKV_C / 128, SEQ_N / 128);
        gemm_f16<<<grid, 128, GEMM_SMEM>>>(xt, wq, nullptr, qkv,
                                           SEQ_N, QKV_C, MODEL_C, 1);
    }
    {   // causal attention -> fp16 scratch
        dim3 grid(SEQ_N / 64, HEADS);
        flash_f16<<<grid, 128, ATT_SMEM>>>(qkv, attn);
    }
    {   // output projection + bias -> fp32 out
        dim3 grid(MODEL_C / 128, SEQ_N / 128);
        gemm_f16<<<grid, 128, GEMM_SMEM>>>(attn, wp, b_proj, out,
                                           SEQ_N, MODEL_C, MODEL_C, 0);
    }
}